// round 12
// baseline (speedup 1.0000x reference)
#include <cuda_runtime.h>
#include <cuda_fp16.h>
#include <cstdint>

// ---------------- problem constants ----------------
#define Dm 256
#define Hh 8
#define HD 32
#define Ll 4
#define Pp 4
#define Bb 32
#define NQ 100
#define Nn (Bb*NQ)          // 3200
#define T_TOTAL 3840
#define LP 16
#define HLP 128

// ---------------- device scratch ----------------
__device__ float g_value[(size_t)Bb * T_TOTAL * Dm];   // ~126MB
__device__ float g_off[Nn * HLP];
__device__ float g_awl[Nn * HLP];
__device__ float g_hsproj[Nn * Dm];
__device__ float g_attnres[Nn * Dm];
__device__ float g_gates[Nn * 4 * Dm];
// weights: single fp16
__device__ __half g_Bf[Dm * Dm];        // W_value^T [n][k]
__device__ __half g_Gf[1024 * 1024];    // [Wih|Whh] [j][k]
__device__ __half g_Cf[256 * 32];       // Wctx^T [e][d]
__device__ __half g_Pf[512 * 512];      // proj B [n][k]

__device__ __forceinline__ float tanh_fast(float x) {
    float e = __expf(2.0f * x);
    return 1.0f - 2.0f / (e + 1.0f);
}
__device__ __forceinline__ float tanha(float x) {
    float y;
    asm("tanh.approx.f32 %0, %1;" : "=f"(y) : "f"(x));
    return y;
}
__device__ __forceinline__ float sigm(float x) {
    return 1.0f / (1.0f + __expf(-x));
}
__device__ __forceinline__ uint32_t smem_u32(const void* p) {
    uint32_t a;
    asm("{ .reg .u64 t; cvta.to.shared.u64 t, %1; cvt.u32.u64 %0, t; }"
        : "=r"(a) : "l"(p));
    return a;
}

// ---------------- mma.sync / ldmatrix (fp16) ----------------
__device__ __forceinline__ void ldm_x4(uint32_t* r, uint32_t addr) {
    asm volatile("ldmatrix.sync.aligned.m8n8.x4.shared.b16 {%0,%1,%2,%3}, [%4];"
        : "=r"(r[0]), "=r"(r[1]), "=r"(r[2]), "=r"(r[3]) : "r"(addr));
}
#define MMAH(d, a, b) \
    asm volatile("mma.sync.aligned.m16n8k16.row.col.f32.f16.f16.f32 " \
        "{%0,%1,%2,%3}, {%4,%5,%6,%7}, {%8,%9}, {%0,%1,%2,%3};" \
        : "+f"((d)[0]), "+f"((d)[1]), "+f"((d)[2]), "+f"((d)[3]) \
        : "r"((a)[0]), "r"((a)[1]), "r"((a)[2]), "r"((a)[3]), \
          "r"((b)[0]), "r"((b)[1]))

// single-term chunk: A x B, both fp16. warp tile 32m x (NT2*16)n
template<int NT2, int KS>
__device__ __forceinline__ void mma_chunk1(
    uint32_t aF, uint32_t bF,
    uint32_t stride2, int wm, int wn, int lane, float* acc)
{
    int arow = lane & 15, acol8 = (lane >> 4) * 8;
    int brow = ((lane >> 4) & 1) * 8 + (lane & 7);
    int bcol8 = ((lane >> 3) & 1) * 8;
#pragma unroll
    for (int ks = 0; ks < KS; ks++) {
        uint32_t Af[2][4], B[NT2][4];
#pragma unroll
        for (int mt = 0; mt < 2; mt++) {
            uint32_t off = (uint32_t)(wm + mt * 16 + arow) * stride2
                         + (uint32_t)(ks * 16 + acol8) * 2;
            ldm_x4(Af[mt], aF + off);
        }
#pragma unroll
        for (int nt2 = 0; nt2 < NT2; nt2++) {
            uint32_t off = (uint32_t)(wn + nt2 * 16 + brow) * stride2
                         + (uint32_t)(ks * 16 + bcol8) * 2;
            ldm_x4(B[nt2], bF + off);
        }
#pragma unroll
        for (int mt = 0; mt < 2; mt++)
#pragma unroll
            for (int nt = 0; nt < 2 * NT2; nt++)
                MMAH(acc + (mt * 2 * NT2 + nt) * 4, Af[mt],
                     (&B[nt >> 1][(nt & 1) * 2]));
    }
}

#define STR 72
// big-tile GEMM smem (BM=128, BN=128): A 18432, B 18432
#define OFF_AF 0
#define OFF_BF 18432
#define GEMM2_SMEM 36864
// value: A 9216, B 36864
#define V_AF 0
#define V_BF 9216
#define V_SMEM 46080

// fp32 row staging: convert 8 floats -> 8 halves -> uint4
__device__ __forceinline__ uint4 cvt8(const float* s) {
    float4 v0 = *(const float4*)s;
    float4 v1 = *(const float4*)(s + 4);
    __half hh[8];
    hh[0] = __float2half_rn(v0.x); hh[1] = __float2half_rn(v0.y);
    hh[2] = __float2half_rn(v0.z); hh[3] = __float2half_rn(v0.w);
    hh[4] = __float2half_rn(v1.x); hh[5] = __float2half_rn(v1.y);
    hh[6] = __float2half_rn(v1.z); hh[7] = __float2half_rn(v1.w);
    return *(uint4*)hh;
}

// =====================================================================
// K0a: prep W_value -> fp16 (transposed)
// =====================================================================
__global__ __launch_bounds__(256) void k_prep_B(const float* __restrict__ Wvalue)
{
    int idx = blockIdx.x * 256 + threadIdx.x;   // < 65536
    int n = idx >> 8, k = idx & 255;
    g_Bf[idx] = __float2half_rn(Wvalue[k * Dm + n]);
}

// =====================================================================
// K0b: prep remaining weights -> fp16
// =====================================================================
__global__ __launch_bounds__(256) void k_prep_rest(
    const float* __restrict__ Wih, const float* __restrict__ Whh,
    const float* __restrict__ Wctx,
    const float* __restrict__ Woff, const float* __restrict__ Waw,
    const float* __restrict__ Whs)
{
    int idx = blockIdx.x * 256 + threadIdx.x;
    if (idx < 1048576) {
        int j = idx >> 10, k = idx & 1023;
        float v = (k < 768) ? Wih[(size_t)j * 768 + k]
                            : Whh[(size_t)j * 256 + (k - 768)];
        g_Gf[idx] = __float2half_rn(v);
    } else if (idx < 1048576 + 8192) {
        int i = idx - 1048576;
        int e = i >> 5, k = i & 31;
        g_Cf[i] = __float2half_rn(Wctx[k * 256 + e]);
    } else if (idx < 1056768 + 262144) {
        int i = idx - 1056768;
        int n = i >> 9, k = i & 511;
        float v;
        if (n < 128)      v = Woff[k * 128 + n];
        else if (n < 256) v = Waw[k * 128 + (n - 128)];
        else              v = (k < 256) ? Whs[k * 256 + (n - 256)] : 0.f;
        g_Pf[i] = __float2half_rn(v);
    }
}

// =====================================================================
// K1: value GEMM (fp16 1-term). M=122880, N=256, K=256. grid 1920, BM=64
// =====================================================================
__global__ __launch_bounds__(256, 2) void k_value_mma(
    const float* __restrict__ A, const float* __restrict__ bias)
{
    extern __shared__ char smem[];
    uint32_t sb = smem_u32(smem);
    int tid = threadIdx.x;
    int w = tid >> 5, lane = tid & 31;
    int wm = (w >> 2) * 32, wn = (w & 3) * 64;
    int row0 = blockIdx.x * 64;

    float acc[64];
#pragma unroll
    for (int i = 0; i < 64; i++) acc[i] = 0.f;

    __half* sAf = (__half*)(smem + V_AF);
    __half* sBf = (__half*)(smem + V_BF);

    uint4 pfA[2];
    auto ldA = [&](int c) {
#pragma unroll
        for (int i = 0; i < 2; i++) {
            int g = tid + i * 256;
            int m = g >> 3, kg = g & 7;
            pfA[i] = cvt8(A + (size_t)(row0 + m) * Dm + c * 64 + kg * 8);
        }
    };
    auto stsA = [&]() {
#pragma unroll
        for (int i = 0; i < 2; i++) {
            int g = tid + i * 256;
            int m = g >> 3, kg = g & 7;
            *(uint4*)&sAf[m * STR + kg * 8] = pfA[i];
        }
    };

    ldA(0);
    for (int c = 0; c < 4; c++) {
        stsA();
        for (int g = tid; g < 2048; g += 256) {
            int n = g >> 3, kg = g & 7;
            int gi = n * Dm + c * 64 + kg * 8;
            *(uint4*)&sBf[n * STR + kg * 8] = *(const uint4*)&g_Bf[gi];
        }
        __syncthreads();
        if (c < 3) ldA(c + 1);
        mma_chunk1<4, 4>(sb + V_AF, sb + V_BF, STR * 2, wm, wn, lane, acc);
        __syncthreads();
    }

#pragma unroll
    for (int mt = 0; mt < 2; mt++)
#pragma unroll
        for (int nt = 0; nt < 8; nt++) {
            float* a4 = &acc[(mt * 8 + nt) * 4];
            int r = row0 + wm + mt * 16 + (lane >> 2);
            int cg = wn + nt * 8 + (lane & 3) * 2;
            float b0 = __ldg(&bias[cg]), b1 = __ldg(&bias[cg + 1]);
            *(float2*)&g_value[(size_t)r * Dm + cg] =
                make_float2(a4[0] + b0, a4[1] + b1);
            *(float2*)&g_value[(size_t)(r + 8) * Dm + cg] =
                make_float2(a4[2] + b0, a4[3] + b1);
        }
}

// =====================================================================
// K2: proj GEMM, BM=128 x BN=128. grid (4,25)
// =====================================================================
__global__ __launch_bounds__(256, 2) void k_proj_mma(
    const float* __restrict__ h0, const float* __restrict__ query,
    const float* __restrict__ boff, const float* __restrict__ baw,
    const float* __restrict__ bhs,  const float* __restrict__ bctx)
{
    extern __shared__ char smem[];
    uint32_t sb = smem_u32(smem);
    int tid = threadIdx.x;
    int w = tid >> 5, lane = tid & 31;
    int wm = (w >> 1) * 32, wn = (w & 1) * 64;
    int row0 = blockIdx.y * 128;
    int col0 = blockIdx.x * 128;

    float acc[64];
#pragma unroll
    for (int i = 0; i < 64; i++) acc[i] = 0.f;

    __half* sAf = (__half*)(smem + OFF_AF);
    __half* sBf = (__half*)(smem + OFF_BF);

    for (int c = 0; c < 8; c++) {
        const float* src = (c < 4) ? h0 : query;
        int kkb = (c & 3) * 64;
        for (int g = tid; g < 1024; g += 256) {
            int m = g >> 3, kg = g & 7;
            *(uint4*)&sAf[m * STR + kg * 8] =
                cvt8(src + (size_t)(row0 + m) * Dm + kkb + kg * 8);
        }
        for (int g = tid; g < 1024; g += 256) {
            int n = g >> 3, kg = g & 7;
            int gi = (col0 + n) * 512 + c * 64 + kg * 8;
            *(uint4*)&sBf[n * STR + kg * 8] = *(const uint4*)&g_Pf[gi];
        }
        __syncthreads();
        mma_chunk1<4, 4>(sb + OFF_AF, sb + OFF_BF, STR * 2, wm, wn, lane, acc);
        __syncthreads();
    }

    int bx = blockIdx.x;
#pragma unroll
    for (int mt = 0; mt < 2; mt++)
#pragma unroll
        for (int nt = 0; nt < 8; nt++) {
            float* a4 = &acc[(mt * 8 + nt) * 4];
            int r = row0 + wm + mt * 16 + (lane >> 2);
            int cl = wn + nt * 8 + (lane & 3) * 2;
            if (bx == 0) {
                float b0 = __ldg(&boff[cl]), b1 = __ldg(&boff[cl + 1]);
                *(float2*)&g_off[r * 128 + cl] = make_float2(a4[0] + b0, a4[1] + b1);
                *(float2*)&g_off[(r + 8) * 128 + cl] = make_float2(a4[2] + b0, a4[3] + b1);
            } else if (bx == 1) {
                float b0 = __ldg(&baw[cl]), b1 = __ldg(&baw[cl + 1]);
                *(float2*)&g_awl[r * 128 + cl] = make_float2(a4[0] + b0, a4[1] + b1);
                *(float2*)&g_awl[(r + 8) * 128 + cl] = make_float2(a4[2] + b0, a4[3] + b1);
            } else {
                int col = (bx - 2) * 128 + cl;
                float b0 = __ldg(&bhs[col]) + __ldg(&bctx[col]);
                float b1 = __ldg(&bhs[col + 1]) + __ldg(&bctx[col + 1]);
                *(float2*)&g_hsproj[r * 256 + col] = make_float2(a4[0] + b0, a4[1] + b1);
                *(float2*)&g_hsproj[(r + 8) * 256 + col] = make_float2(a4[2] + b0, a4[3] + b1);
            }
        }
}

// =====================================================================
// K3: sample + additive attention (fp16 1-term) — unchanged
// =====================================================================
#define A3STR 40
#define S3_AF  0
#define S3_BF  10240
#define S3_ADD 30720
#define S3_WA  31744
#define S3_AW  32768
#define S3_SC  33280
#define S3_SMEM 33792

__global__ __launch_bounds__(256) void k_sample_attn(
    const float* __restrict__ rp,
    const float* __restrict__ Walpha)
{
    extern __shared__ char sm3[];
    __half* sAf3 = (__half*)(sm3 + S3_AF);
    __half* sBf3 = (__half*)(sm3 + S3_BF);
    float* add_s = (float*)(sm3 + S3_ADD);
    float* Wa_s  = (float*)(sm3 + S3_WA);
    float* aw_s  = (float*)(sm3 + S3_AW);
    float* sc_s  = (float*)(sm3 + S3_SC);

    int n = blockIdx.x;
    int tid = threadIdx.x;
    int w = tid >> 5, lane = tid & 31;
    int b = n / NQ;

    for (int g = tid; g < 1024; g += 256) {
        int r = g >> 2, kg = (g & 3) * 8;
        *(uint4*)&sBf3[r * A3STR + kg] = *(const uint4*)&g_Cf[r * 32 + kg];
    }
    if (tid < 128) { aw_s[tid] = g_awl[n * 128 + tid]; sc_s[tid] = 0.f; }
    add_s[tid] = g_hsproj[n * 256 + tid];
    Wa_s[tid] = Walpha[tid];
    __syncthreads();

    if (lane < 16) {
        float v = aw_s[w * 16 + lane];
        float mx = v;
#pragma unroll
        for (int o = 8; o > 0; o >>= 1)
            mx = fmaxf(mx, __shfl_xor_sync(0x0000ffffu, mx, o, 16));
        float ev = __expf(v - mx);
        float s = ev;
#pragma unroll
        for (int o = 8; o > 0; o >>= 1)
            s += __shfl_xor_sync(0x0000ffffu, s, o, 16);
        aw_s[w * 16 + lane] = ev / s;
    }
    __syncthreads();

    {
        const int TLS[4]    = {2048, 1024, 512, 256};
        const int STARTS[4] = {0, 2048, 3072, 3584};
        int pair = tid >> 1, half = tid & 1;
        int h2 = pair >> 4, lp = pair & 15, l = lp >> 2;
        int Tl = TLS[l], st = STARTS[l];
        float ref = rp[n * Ll + l];
        float off = g_off[n * HLP + pair];
        float aw = aw_s[pair];
        float x = ref * (float)Tl + off - 0.5f;
        float xf = floorf(x);
        float w1 = x - xf, w0 = 1.0f - w1;
        int i0 = (int)xf, i1 = i0 + 1;
        float wa0 = aw * w0 * ((i0 >= 0 && i0 < Tl) ? 1.f : 0.f);
        float wa1 = aw * w1 * ((i1 >= 0 && i1 < Tl) ? 1.f : 0.f);
        int c0i = min(max(i0, 0), Tl - 1);
        int c1i = min(max(i1, 0), Tl - 1);
        size_t base0 = ((size_t)(b * T_TOTAL + st + c0i)) * Dm + h2 * HD + half * 16;
        size_t base1 = ((size_t)(b * T_TOTAL + st + c1i)) * Dm + h2 * HD + half * 16;
#pragma unroll
        for (int q4 = 0; q4 < 4; q4++) {
            float4 v0 = *(const float4*)&g_value[base0 + q4 * 4];
            float4 v1 = *(const float4*)&g_value[base1 + q4 * 4];
            __half hh[4];
            hh[0] = __float2half_rn(wa0 * v0.x + wa1 * v1.x);
            hh[1] = __float2half_rn(wa0 * v0.y + wa1 * v1.y);
            hh[2] = __float2half_rn(wa0 * v0.z + wa1 * v1.z);
            hh[3] = __float2half_rn(wa0 * v0.w + wa1 * v1.w);
            int d = half * 16 + q4 * 4;
            *(uint2*)&sAf3[pair * A3STR + d] = *(uint2*)hh;
        }
    }
    __syncthreads();

    uint32_t aF = smem_u32(sAf3);
    uint32_t bF = smem_u32(sBf3);
    int wm = (w >> 1) * 32, wnl = (w & 1) * 32;
    float scoreacc[2][2] = {{0.f, 0.f}, {0.f, 0.f}};

#pragma unroll
    for (int pass = 0; pass < 4; pass++) {
        uint32_t boff2 = (uint32_t)(pass * 64 * A3STR * 2);
        float acc[32];
#pragma unroll
        for (int i = 0; i < 32; i++) acc[i] = 0.f;
        mma_chunk1<2, 2>(aF, bF + boff2, A3STR * 2, wm, wnl, lane, acc);
#pragma unroll
        for (int mt = 0; mt < 2; mt++)
#pragma unroll
            for (int nt = 0; nt < 4; nt++) {
                float* a4 = &acc[(mt * 4 + nt) * 4];
                int e0 = pass * 64 + wnl + nt * 8 + (lane & 3) * 2;
                scoreacc[mt][0] += tanha(a4[0] + add_s[e0]) * Wa_s[e0];
                scoreacc[mt][0] += tanha(a4[1] + add_s[e0 + 1]) * Wa_s[e0 + 1];
                scoreacc[mt][1] += tanha(a4[2] + add_s[e0]) * Wa_s[e0];
                scoreacc[mt][1] += tanha(a4[3] + add_s[e0 + 1]) * Wa_s[e0 + 1];
            }
    }

#pragma unroll
    for (int mt = 0; mt < 2; mt++) {
        float s0 = scoreacc[mt][0], s1 = scoreacc[mt][1];
        s0 += __shfl_xor_sync(0xffffffffu, s0, 1);
        s0 += __shfl_xor_sync(0xffffffffu, s0, 2);
        s1 += __shfl_xor_sync(0xffffffffu, s1, 1);
        s1 += __shfl_xor_sync(0xffffffffu, s1, 2);
        if ((lane & 3) == 0) {
            atomicAdd(&sc_s[wm + mt * 16 + (lane >> 2)], s0);
            atomicAdd(&sc_s[wm + mt * 16 + 8 + (lane >> 2)], s1);
        }
    }
    __syncthreads();

    if (lane < 16) {
        float v = sc_s[w * 16 + lane];
        float mx = v;
#pragma unroll
        for (int o = 8; o > 0; o >>= 1)
            mx = fmaxf(mx, __shfl_xor_sync(0x0000ffffu, mx, o, 16));
        float ev = __expf(v - mx);
        float s = ev;
#pragma unroll
        for (int o = 8; o > 0; o >>= 1)
            s += __shfl_xor_sync(0x0000ffffu, s, o, 16);
        sc_s[w * 16 + lane] = ev / s;
    }
    __syncwarp();

    {
        float accw = 0.f;
#pragma unroll
        for (int p = 0; p < 16; p++) {
            int r = (w * 16 + p) * A3STR + lane;
            accw += sc_s[w * 16 + p] * __half2float(sAf3[r]);
        }
        g_attnres[(size_t)n * Dm + w * HD + lane] = accw;
    }
}

// =====================================================================
// K4a/K4b: gates GEMMs, BM=128 x BN=128. grid (8,25)
// =====================================================================
template<int NCHUNK, bool ACCUM>
__device__ __forceinline__ void gates_core(
    const float* token, const float* query, const float* h0, int tid)
{
    extern __shared__ char smem[];
    uint32_t sb = smem_u32(smem);
    int w = tid >> 5, lane = tid & 31;
    int wm = (w >> 1) * 32, wn = (w & 1) * 64;
    int row0 = blockIdx.y * 128;
    int col0 = blockIdx.x * 128;

    float acc[64];
#pragma unroll
    for (int i = 0; i < 64; i++) acc[i] = 0.f;

    __half* sAf = (__half*)(smem + OFF_AF);
    __half* sBf = (__half*)(smem + OFF_BF);

    const int segbase[3] = {0, 512, 768};
    for (int c = 0; c < NCHUNK; c++) {
        const float* src;
        int kcol;
        if (ACCUM) { src = g_attnres; kcol = 256 + c * 64; }
        else {
            int seg = c >> 2;
            src = (seg == 0) ? token : (seg == 1) ? query : h0;
            kcol = segbase[seg] + (c & 3) * 64;
        }
        int kkb = (c & 3) * 64;
        for (int g = tid; g < 1024; g += 256) {
            int m = g >> 3, kg = g & 7;
            *(uint4*)&sAf[m * STR + kg * 8] =
                cvt8(src + (size_t)(row0 + m) * Dm + kkb + kg * 8);
        }
        for (int g = tid; g < 1024; g += 256) {
            int n = g >> 3, kg = g & 7;
            size_t gi = (size_t)(col0 + n) * 1024 + kcol + kg * 8;
            *(uint4*)&sBf[n * STR + kg * 8] = *(const uint4*)&g_Gf[gi];
        }
        __syncthreads();
        mma_chunk1<4, 4>(sb + OFF_AF, sb + OFF_BF, STR * 2, wm, wn, lane, acc);
        __syncthreads();
    }

#pragma unroll
    for (int mt = 0; mt < 2; mt++)
#pragma unroll
        for (int nt = 0; nt < 8; nt++) {
            float* a4 = &acc[(mt * 8 + nt) * 4];
            int r = row0 + wm + mt * 16 + (lane >> 2);
            int cg = col0 + wn + nt * 8 + (lane & 3) * 2;
            float* p0 = &g_gates[(size_t)r * 1024 + cg];
            float* p1 = &g_gates[(size_t)(r + 8) * 1024 + cg];
            if (ACCUM) {
                float2 o0 = *(float2*)p0, o1 = *(float2*)p1;
                *(float2*)p0 = make_float2(o0.x + a4[0], o0.y + a4[1]);
                *(float2*)p1 = make_float2(o1.x + a4[2], o1.y + a4[3]);
            } else {
                *(float2*)p0 = make_float2(a4[0], a4[1]);
                *(float2*)p1 = make_float2(a4[2], a4[3]);
            }
        }
}

__global__ __launch_bounds__(256, 2) void k_gates768(
    const float* __restrict__ token, const float* __restrict__ query,
    const float* __restrict__ h0)
{
    gates_core<12, false>(token, query, h0, threadIdx.x);
}
__global__ __launch_bounds__(256, 2) void k_gates256()
{
    gates_core<4, true>(nullptr, nullptr, nullptr, threadIdx.x);
}

// =====================================================================
// K5: LSTM elementwise + output writes
// =====================================================================
__global__ __launch_bounds__(256) void k_lstm_ew(
    const float* __restrict__ c0, float* __restrict__ out, int write3)
{
    int n = blockIdx.x;
    int d = threadIdx.x;
    size_t g = (size_t)n * 1024;
    float gi = g_gates[g + d];
    float gf = g_gates[g + 256 + d];
    float gg = g_gates[g + 512 + d];
    float go = g_gates[g + 768 + d];
    float cprev = c0[(size_t)n * Dm + d];
    float cnew = sigm(gf) * cprev + sigm(gi) * tanh_fast(gg);
    float hnew = sigm(go) * tanh_fast(cnew);
    size_t idx = (size_t)n * Dm + d;
    out[idx] = hnew;
    if (write3) {
        out[(size_t)Nn * Dm + idx]     = hnew;
        out[(size_t)2 * Nn * Dm + idx] = cnew;
    }
}

// ---------------- streams/events (static init, outside capture) ----------
static cudaStream_t g_s1 = nullptr;
static cudaEvent_t g_e0 = nullptr, g_e_proj = nullptr, g_e_g768 = nullptr;
static bool g_streams_ok = false;
static struct StreamInit {
    StreamInit() {
        bool ok = true;
        ok &= (cudaStreamCreateWithFlags(&g_s1, cudaStreamNonBlocking) == cudaSuccess);
        ok &= (cudaEventCreateWithFlags(&g_e0, cudaEventDisableTiming) == cudaSuccess);
        ok &= (cudaEventCreateWithFlags(&g_e_proj, cudaEventDisableTiming) == cudaSuccess);
        ok &= (cudaEventCreateWithFlags(&g_e_g768, cudaEventDisableTiming) == cudaSuccess);
        g_streams_ok = ok;
    }
} g_stream_init;

// =====================================================================
// launch
// =====================================================================
extern "C" void kernel_launch(void* const* d_in, const int* in_sizes, int n_in,
                              void* d_out, int out_size)
{
    const float* token  = (const float*)d_in[0];
    const float* h0     = (const float*)d_in[1];
    const float* c0     = (const float*)d_in[2];
    const float* query  = (const float*)d_in[3];
    const float* rp     = (const float*)d_in[4];
    const float* ehs    = (const float*)d_in[5];
    const float* Wvalue = (const float*)d_in[8];
    const float* bvalue = (const float*)d_in[9];
    const float* Woff   = (const float*)d_in[10];
    const float* boff   = (const float*)d_in[11];
    const float* Waw    = (const float*)d_in[12];
    const float* baw    = (const float*)d_in[13];
    const float* Wctx   = (const float*)d_in[14];
    const float* bctx   = (const float*)d_in[15];
    const float* Whs    = (const float*)d_in[16];
    const float* bhs    = (const float*)d_in[17];
    const float* Walpha = (const float*)d_in[18];
    const float* Wih    = (const float*)d_in[20];
    const float* Whh    = (const float*)d_in[21];
    float* out = (float*)d_out;

    cudaFuncSetAttribute(k_value_mma,
                         cudaFuncAttributeMaxDynamicSharedMemorySize, V_SMEM);
    cudaFuncSetAttribute(k_proj_mma,
                         cudaFuncAttributeMaxDynamicSharedMemorySize, GEMM2_SMEM);
    cudaFuncSetAttribute(k_sample_attn,
                         cudaFuncAttributeMaxDynamicSharedMemorySize, S3_SMEM);
    cudaFuncSetAttribute(k_gates768,
                         cudaFuncAttributeMaxDynamicSharedMemorySize, GEMM2_SMEM);
    cudaFuncSetAttribute(k_gates256,
                         cudaFuncAttributeMaxDynamicSharedMemorySize, GEMM2_SMEM);

    int write3 = (out_size >= 3 * Nn * Dm) ? 1 : 0;
    const int PREP_REST_BLOCKS = (1048576 + 8192 + 262144 + 255) / 256;  // 5152

    if (g_streams_ok) {
        k_prep_B<<<256, 256>>>(Wvalue);
        cudaEventRecord(g_e0, 0);
        cudaStreamWaitEvent(g_s1, g_e0, 0);
        k_prep_rest<<<PREP_REST_BLOCKS, 256, 0, g_s1>>>(Wih, Whh, Wctx, Woff, Waw, Whs);
        k_proj_mma<<<dim3(4, 25), 256, GEMM2_SMEM, g_s1>>>(h0, query, boff, baw, bhs, bctx);
        cudaEventRecord(g_e_proj, g_s1);
        k_gates768<<<dim3(8, 25), 256, GEMM2_SMEM, g_s1>>>(token, query, h0);
        cudaEventRecord(g_e_g768, g_s1);
        k_value_mma<<<1920, 256, V_SMEM>>>(ehs, bvalue);
        cudaStreamWaitEvent(0, g_e_proj, 0);
        k_sample_attn<<<Nn, 256, S3_SMEM>>>(rp, Walpha);
        cudaStreamWaitEvent(0, g_e_g768, 0);
        k_gates256<<<dim3(8, 25), 256, GEMM2_SMEM>>>();
        k_lstm_ew<<<Nn, 256>>>(c0, out, write3);
    } else {
        k_prep_B<<<256, 256>>>(Wvalue);
        k_prep_rest<<<PREP_REST_BLOCKS, 256>>>(Wih, Whh, Wctx, Woff, Waw, Whs);
        k_proj_mma<<<dim3(4, 25), 256, GEMM2_SMEM>>>(h0, query, boff, baw, bhs, bctx);
        k_gates768<<<dim3(8, 25), 256, GEMM2_SMEM>>>(token, query, h0);
        k_value_mma<<<1920, 256, V_SMEM>>>(ehs, bvalue);
        k_sample_attn<<<Nn, 256, S3_SMEM>>>(rp, Walpha);
        k_gates256<<<dim3(8, 25), 256, GEMM2_SMEM>>>();
        k_lstm_ew<<<Nn, 256>>>(c0, out, write3);
    }
}

// round 13
// speedup vs baseline: 1.1110x; 1.1110x over previous
#include <cuda_runtime.h>
#include <cuda_fp16.h>
#include <cstdint>

// ---------------- problem constants ----------------
#define Dm 256
#define Hh 8
#define HD 32
#define Ll 4
#define Pp 4
#define Bb 32
#define NQ 100
#define Nn (Bb*NQ)          // 3200
#define T_TOTAL 3840
#define LP 16
#define HLP 128

// ---------------- device scratch ----------------
__device__ __half g_value_h[(size_t)Bb * T_TOTAL * Dm];   // ~63MB (fp16)
__device__ float g_off[Nn * HLP];
__device__ float g_awl[Nn * HLP];
__device__ float g_hsproj[Nn * Dm];
__device__ float g_attnres[Nn * Dm];
__device__ float g_gates[Nn * 4 * Dm];
// weights: single fp16
__device__ __half g_Bf[Dm * Dm];        // W_value^T [n][k]
__device__ __half g_Gf[1024 * 1024];    // [Wih|Whh] [j][k]
__device__ __half g_Cf[256 * 32];       // Wctx^T [e][d]
__device__ __half g_Pf[512 * 512];      // proj B [n][k]

__device__ __forceinline__ float tanh_fast(float x) {
    float e = __expf(2.0f * x);
    return 1.0f - 2.0f / (e + 1.0f);
}
__device__ __forceinline__ float tanha(float x) {
    float y;
    asm("tanh.approx.f32 %0, %1;" : "=f"(y) : "f"(x));
    return y;
}
__device__ __forceinline__ float sigm(float x) {
    return 1.0f / (1.0f + __expf(-x));
}
__device__ __forceinline__ uint32_t smem_u32(const void* p) {
    uint32_t a;
    asm("{ .reg .u64 t; cvta.to.shared.u64 t, %1; cvt.u32.u64 %0, t; }"
        : "=r"(a) : "l"(p));
    return a;
}

// ---------------- mma.sync / ldmatrix (fp16) ----------------
__device__ __forceinline__ void ldm_x4(uint32_t* r, uint32_t addr) {
    asm volatile("ldmatrix.sync.aligned.m8n8.x4.shared.b16 {%0,%1,%2,%3}, [%4];"
        : "=r"(r[0]), "=r"(r[1]), "=r"(r[2]), "=r"(r[3]) : "r"(addr));
}
#define MMAH(d, a, b) \
    asm volatile("mma.sync.aligned.m16n8k16.row.col.f32.f16.f16.f32 " \
        "{%0,%1,%2,%3}, {%4,%5,%6,%7}, {%8,%9}, {%0,%1,%2,%3};" \
        : "+f"((d)[0]), "+f"((d)[1]), "+f"((d)[2]), "+f"((d)[3]) \
        : "r"((a)[0]), "r"((a)[1]), "r"((a)[2]), "r"((a)[3]), \
          "r"((b)[0]), "r"((b)[1]))

// single-term chunk: A x B, both fp16. warp tile 32m x (NT2*16)n
template<int NT2, int KS>
__device__ __forceinline__ void mma_chunk1(
    uint32_t aF, uint32_t bF,
    uint32_t stride2, int wm, int wn, int lane, float* acc)
{
    int arow = lane & 15, acol8 = (lane >> 4) * 8;
    int brow = ((lane >> 4) & 1) * 8 + (lane & 7);
    int bcol8 = ((lane >> 3) & 1) * 8;
#pragma unroll
    for (int ks = 0; ks < KS; ks++) {
        uint32_t Af[2][4], B[NT2][4];
#pragma unroll
        for (int mt = 0; mt < 2; mt++) {
            uint32_t off = (uint32_t)(wm + mt * 16 + arow) * stride2
                         + (uint32_t)(ks * 16 + acol8) * 2;
            ldm_x4(Af[mt], aF + off);
        }
#pragma unroll
        for (int nt2 = 0; nt2 < NT2; nt2++) {
            uint32_t off = (uint32_t)(wn + nt2 * 16 + brow) * stride2
                         + (uint32_t)(ks * 16 + bcol8) * 2;
            ldm_x4(B[nt2], bF + off);
        }
#pragma unroll
        for (int mt = 0; mt < 2; mt++)
#pragma unroll
            for (int nt = 0; nt < 2 * NT2; nt++)
                MMAH(acc + (mt * 2 * NT2 + nt) * 4, Af[mt],
                     (&B[nt >> 1][(nt & 1) * 2]));
    }
}

#define STR 72
// generic GEMM smem (BM=64, BN=128): A 9216, B 18432
#define OFF_AF 0
#define OFF_BF 9216
#define GEMM_SMEM 27648
// value: A 9216, B 36864
#define V_AF 0
#define V_BF 9216
#define V_SMEM 46080

// fp32 row staging: convert 8 floats -> 8 halves -> uint4
__device__ __forceinline__ uint4 cvt8(const float* s) {
    float4 v0 = *(const float4*)s;
    float4 v1 = *(const float4*)(s + 4);
    __half hh[8];
    hh[0] = __float2half_rn(v0.x); hh[1] = __float2half_rn(v0.y);
    hh[2] = __float2half_rn(v0.z); hh[3] = __float2half_rn(v0.w);
    hh[4] = __float2half_rn(v1.x); hh[5] = __float2half_rn(v1.y);
    hh[6] = __float2half_rn(v1.z); hh[7] = __float2half_rn(v1.w);
    return *(uint4*)hh;
}

// =====================================================================
// K0a: prep W_value -> fp16 (transposed)
// =====================================================================
__global__ __launch_bounds__(256) void k_prep_B(const float* __restrict__ Wvalue)
{
    int idx = blockIdx.x * 256 + threadIdx.x;   // < 65536
    int n = idx >> 8, k = idx & 255;
    g_Bf[idx] = __float2half_rn(Wvalue[k * Dm + n]);
}

// =====================================================================
// K0b: prep remaining weights -> fp16
// =====================================================================
__global__ __launch_bounds__(256) void k_prep_rest(
    const float* __restrict__ Wih, const float* __restrict__ Whh,
    const float* __restrict__ Wctx,
    const float* __restrict__ Woff, const float* __restrict__ Waw,
    const float* __restrict__ Whs)
{
    int idx = blockIdx.x * 256 + threadIdx.x;
    if (idx < 1048576) {
        int j = idx >> 10, k = idx & 1023;
        float v = (k < 768) ? Wih[(size_t)j * 768 + k]
                            : Whh[(size_t)j * 256 + (k - 768)];
        g_Gf[idx] = __float2half_rn(v);
    } else if (idx < 1048576 + 8192) {
        int i = idx - 1048576;
        int e = i >> 5, k = i & 31;
        g_Cf[i] = __float2half_rn(Wctx[k * 256 + e]);
    } else if (idx < 1056768 + 262144) {
        int i = idx - 1056768;
        int n = i >> 9, k = i & 511;
        float v;
        if (n < 128)      v = Woff[k * 128 + n];
        else if (n < 256) v = Waw[k * 128 + (n - 128)];
        else              v = (k < 256) ? Whs[k * 256 + (n - 256)] : 0.f;
        g_Pf[i] = __float2half_rn(v);
    }
}

// =====================================================================
// K1: value GEMM (fp16 1-term, fp16 output). grid 1920, BM=64, BN=256
// =====================================================================
__global__ __launch_bounds__(256, 2) void k_value_mma(
    const float* __restrict__ A, const float* __restrict__ bias)
{
    extern __shared__ char smem[];
    uint32_t sb = smem_u32(smem);
    int tid = threadIdx.x;
    int w = tid >> 5, lane = tid & 31;
    int wm = (w >> 2) * 32, wn = (w & 3) * 64;
    int row0 = blockIdx.x * 64;

    float acc[64];
#pragma unroll
    for (int i = 0; i < 64; i++) acc[i] = 0.f;

    __half* sAf = (__half*)(smem + V_AF);
    __half* sBf = (__half*)(smem + V_BF);

    uint4 pfA[2];
    auto ldA = [&](int c) {
#pragma unroll
        for (int i = 0; i < 2; i++) {
            int g = tid + i * 256;
            int m = g >> 3, kg = g & 7;
            pfA[i] = cvt8(A + (size_t)(row0 + m) * Dm + c * 64 + kg * 8);
        }
    };
    auto stsA = [&]() {
#pragma unroll
        for (int i = 0; i < 2; i++) {
            int g = tid + i * 256;
            int m = g >> 3, kg = g & 7;
            *(uint4*)&sAf[m * STR + kg * 8] = pfA[i];
        }
    };

    ldA(0);
    for (int c = 0; c < 4; c++) {
        stsA();
        for (int g = tid; g < 2048; g += 256) {
            int n = g >> 3, kg = g & 7;
            int gi = n * Dm + c * 64 + kg * 8;
            *(uint4*)&sBf[n * STR + kg * 8] = *(const uint4*)&g_Bf[gi];
        }
        __syncthreads();
        if (c < 3) ldA(c + 1);
        mma_chunk1<4, 4>(sb + V_AF, sb + V_BF, STR * 2, wm, wn, lane, acc);
        __syncthreads();
    }

    // epilogue: +bias, store fp16
#pragma unroll
    for (int mt = 0; mt < 2; mt++)
#pragma unroll
        for (int nt = 0; nt < 8; nt++) {
            float* a4 = &acc[(mt * 8 + nt) * 4];
            int r = row0 + wm + mt * 16 + (lane >> 2);
            int cg = wn + nt * 8 + (lane & 3) * 2;
            float b0 = __ldg(&bias[cg]), b1 = __ldg(&bias[cg + 1]);
            *(__half2*)&g_value_h[(size_t)r * Dm + cg] =
                __floats2half2_rn(a4[0] + b0, a4[1] + b1);
            *(__half2*)&g_value_h[(size_t)(r + 8) * Dm + cg] =
                __floats2half2_rn(a4[2] + b0, a4[3] + b1);
        }
}

// =====================================================================
// K2: proj GEMM, BM=64 x BN=128. grid (4,50)
// =====================================================================
__global__ __launch_bounds__(256) void k_proj_mma(
    const float* __restrict__ h0, const float* __restrict__ query,
    const float* __restrict__ boff, const float* __restrict__ baw,
    const float* __restrict__ bhs,  const float* __restrict__ bctx)
{
    extern __shared__ char smem[];
    uint32_t sb = smem_u32(smem);
    int tid = threadIdx.x;
    int w = tid >> 5, lane = tid & 31;
    int wm = (w >> 2) * 32, wn = (w & 3) * 32;
    int row0 = blockIdx.y * 64;
    int col0 = blockIdx.x * 128;

    float acc[32];
#pragma unroll
    for (int i = 0; i < 32; i++) acc[i] = 0.f;

    __half* sAf = (__half*)(smem + OFF_AF);
    __half* sBf = (__half*)(smem + OFF_BF);

    for (int c = 0; c < 8; c++) {
        const float* src = (c < 4) ? h0 : query;
        int kkb = (c & 3) * 64;
        for (int g = tid; g < 512; g += 256) {
            int m = g >> 3, kg = g & 7;
            *(uint4*)&sAf[m * STR + kg * 8] =
                cvt8(src + (size_t)(row0 + m) * Dm + kkb + kg * 8);
        }
        for (int g = tid; g < 1024; g += 256) {
            int n = g >> 3, kg = g & 7;
            int gi = (col0 + n) * 512 + c * 64 + kg * 8;
            *(uint4*)&sBf[n * STR + kg * 8] = *(const uint4*)&g_Pf[gi];
        }
        __syncthreads();
        mma_chunk1<2, 4>(sb + OFF_AF, sb + OFF_BF, STR * 2, wm, wn, lane, acc);
        __syncthreads();
    }

    int bx = blockIdx.x;
#pragma unroll
    for (int mt = 0; mt < 2; mt++)
#pragma unroll
        for (int nt = 0; nt < 4; nt++) {
            float* a4 = &acc[(mt * 4 + nt) * 4];
            int r = row0 + wm + mt * 16 + (lane >> 2);
            int cl = wn + nt * 8 + (lane & 3) * 2;
            if (bx == 0) {
                float b0 = __ldg(&boff[cl]), b1 = __ldg(&boff[cl + 1]);
                *(float2*)&g_off[r * 128 + cl] = make_float2(a4[0] + b0, a4[1] + b1);
                *(float2*)&g_off[(r + 8) * 128 + cl] = make_float2(a4[2] + b0, a4[3] + b1);
            } else if (bx == 1) {
                float b0 = __ldg(&baw[cl]), b1 = __ldg(&baw[cl + 1]);
                *(float2*)&g_awl[r * 128 + cl] = make_float2(a4[0] + b0, a4[1] + b1);
                *(float2*)&g_awl[(r + 8) * 128 + cl] = make_float2(a4[2] + b0, a4[3] + b1);
            } else {
                int col = (bx - 2) * 128 + cl;
                float b0 = __ldg(&bhs[col]) + __ldg(&bctx[col]);
                float b1 = __ldg(&bhs[col + 1]) + __ldg(&bctx[col + 1]);
                *(float2*)&g_hsproj[r * 256 + col] = make_float2(a4[0] + b0, a4[1] + b1);
                *(float2*)&g_hsproj[(r + 8) * 256 + col] = make_float2(a4[2] + b0, a4[3] + b1);
            }
        }
}

// =====================================================================
// K3: sample + additive attention (fp16 value input)
// =====================================================================
#define A3STR 40
#define S3_AF  0
#define S3_BF  10240
#define S3_ADD 30720
#define S3_WA  31744
#define S3_AW  32768
#define S3_SC  33280
#define S3_SMEM 33792

__global__ __launch_bounds__(256) void k_sample_attn(
    const float* __restrict__ rp,
    const float* __restrict__ Walpha)
{
    extern __shared__ char sm3[];
    __half* sAf3 = (__half*)(sm3 + S3_AF);
    __half* sBf3 = (__half*)(sm3 + S3_BF);
    float* add_s = (float*)(sm3 + S3_ADD);
    float* Wa_s  = (float*)(sm3 + S3_WA);
    float* aw_s  = (float*)(sm3 + S3_AW);
    float* sc_s  = (float*)(sm3 + S3_SC);

    int n = blockIdx.x;
    int tid = threadIdx.x;
    int w = tid >> 5, lane = tid & 31;
    int b = n / NQ;

    for (int g = tid; g < 1024; g += 256) {
        int r = g >> 2, kg = (g & 3) * 8;
        *(uint4*)&sBf3[r * A3STR + kg] = *(const uint4*)&g_Cf[r * 32 + kg];
    }
    if (tid < 128) { aw_s[tid] = g_awl[n * 128 + tid]; sc_s[tid] = 0.f; }
    add_s[tid] = g_hsproj[n * 256 + tid];
    Wa_s[tid] = Walpha[tid];
    __syncthreads();

    if (lane < 16) {
        float v = aw_s[w * 16 + lane];
        float mx = v;
#pragma unroll
        for (int o = 8; o > 0; o >>= 1)
            mx = fmaxf(mx, __shfl_xor_sync(0x0000ffffu, mx, o, 16));
        float ev = __expf(v - mx);
        float s = ev;
#pragma unroll
        for (int o = 8; o > 0; o >>= 1)
            s += __shfl_xor_sync(0x0000ffffu, s, o, 16);
        aw_s[w * 16 + lane] = ev / s;
    }
    __syncthreads();

    {
        const int TLS[4]    = {2048, 1024, 512, 256};
        const int STARTS[4] = {0, 2048, 3072, 3584};
        int pair = tid >> 1, half = tid & 1;
        int h2 = pair >> 4, lp = pair & 15, l = lp >> 2;
        int Tl = TLS[l], st = STARTS[l];
        float ref = rp[n * Ll + l];
        float off = g_off[n * HLP + pair];
        float aw = aw_s[pair];
        float x = ref * (float)Tl + off - 0.5f;
        float xf = floorf(x);
        float w1 = x - xf, w0 = 1.0f - w1;
        int i0 = (int)xf, i1 = i0 + 1;
        float wa0 = aw * w0 * ((i0 >= 0 && i0 < Tl) ? 1.f : 0.f);
        float wa1 = aw * w1 * ((i1 >= 0 && i1 < Tl) ? 1.f : 0.f);
        int c0i = min(max(i0, 0), Tl - 1);
        int c1i = min(max(i1, 0), Tl - 1);
        size_t base0 = ((size_t)(b * T_TOTAL + st + c0i)) * Dm + h2 * HD + half * 16;
        size_t base1 = ((size_t)(b * T_TOTAL + st + c1i)) * Dm + h2 * HD + half * 16;
        // read 16 fp16 per row (2x uint4), interpolate in f32, store fp16
        uint4 ua[2], ub[2];
        ua[0] = *(const uint4*)&g_value_h[base0];
        ua[1] = *(const uint4*)&g_value_h[base0 + 8];
        ub[0] = *(const uint4*)&g_value_h[base1];
        ub[1] = *(const uint4*)&g_value_h[base1 + 8];
        const __half2* ha = (const __half2*)ua;
        const __half2* hb = (const __half2*)ub;
        uint4 outv[2];
        __half2* ho = (__half2*)outv;
#pragma unroll
        for (int q2 = 0; q2 < 8; q2++) {
            float2 fa = __half22float2(ha[q2]);
            float2 fb = __half22float2(hb[q2]);
            ho[q2] = __floats2half2_rn(wa0 * fa.x + wa1 * fb.x,
                                       wa0 * fa.y + wa1 * fb.y);
        }
        int d = half * 16;
        *(uint4*)&sAf3[pair * A3STR + d]     = outv[0];
        *(uint4*)&sAf3[pair * A3STR + d + 8] = outv[1];
    }
    __syncthreads();

    uint32_t aF = smem_u32(sAf3);
    uint32_t bF = smem_u32(sBf3);
    int wm = (w >> 1) * 32, wnl = (w & 1) * 32;
    float scoreacc[2][2] = {{0.f, 0.f}, {0.f, 0.f}};

#pragma unroll
    for (int pass = 0; pass < 4; pass++) {
        uint32_t boff2 = (uint32_t)(pass * 64 * A3STR * 2);
        float acc[32];
#pragma unroll
        for (int i = 0; i < 32; i++) acc[i] = 0.f;
        mma_chunk1<2, 2>(aF, bF + boff2, A3STR * 2, wm, wnl, lane, acc);
#pragma unroll
        for (int mt = 0; mt < 2; mt++)
#pragma unroll
            for (int nt = 0; nt < 4; nt++) {
                float* a4 = &acc[(mt * 4 + nt) * 4];
                int e0 = pass * 64 + wnl + nt * 8 + (lane & 3) * 2;
                scoreacc[mt][0] += tanha(a4[0] + add_s[e0]) * Wa_s[e0];
                scoreacc[mt][0] += tanha(a4[1] + add_s[e0 + 1]) * Wa_s[e0 + 1];
                scoreacc[mt][1] += tanha(a4[2] + add_s[e0]) * Wa_s[e0];
                scoreacc[mt][1] += tanha(a4[3] + add_s[e0 + 1]) * Wa_s[e0 + 1];
            }
    }

#pragma unroll
    for (int mt = 0; mt < 2; mt++) {
        float s0 = scoreacc[mt][0], s1 = scoreacc[mt][1];
        s0 += __shfl_xor_sync(0xffffffffu, s0, 1);
        s0 += __shfl_xor_sync(0xffffffffu, s0, 2);
        s1 += __shfl_xor_sync(0xffffffffu, s1, 1);
        s1 += __shfl_xor_sync(0xffffffffu, s1, 2);
        if ((lane & 3) == 0) {
            atomicAdd(&sc_s[wm + mt * 16 + (lane >> 2)], s0);
            atomicAdd(&sc_s[wm + mt * 16 + 8 + (lane >> 2)], s1);
        }
    }
    __syncthreads();

    if (lane < 16) {
        float v = sc_s[w * 16 + lane];
        float mx = v;
#pragma unroll
        for (int o = 8; o > 0; o >>= 1)
            mx = fmaxf(mx, __shfl_xor_sync(0x0000ffffu, mx, o, 16));
        float ev = __expf(v - mx);
        float s = ev;
#pragma unroll
        for (int o = 8; o > 0; o >>= 1)
            s += __shfl_xor_sync(0x0000ffffu, s, o, 16);
        sc_s[w * 16 + lane] = ev / s;
    }
    __syncwarp();

    {
        float accw = 0.f;
#pragma unroll
        for (int p = 0; p < 16; p++) {
            int r = (w * 16 + p) * A3STR + lane;
            accw += sc_s[w * 16 + p] * __half2float(sAf3[r]);
        }
        g_attnres[(size_t)n * Dm + w * HD + lane] = accw;
    }
}

// =====================================================================
// K4a/K4b: gates GEMMs, BM=64 x BN=128. grid (8,50)
// =====================================================================
template<int NCHUNK, bool ACCUM>
__device__ __forceinline__ void gates_core(
    const float* token, const float* query, const float* h0, int tid)
{
    extern __shared__ char smem[];
    uint32_t sb = smem_u32(smem);
    int w = tid >> 5, lane = tid & 31;
    int wm = (w >> 2) * 32, wn = (w & 3) * 32;
    int row0 = blockIdx.y * 64;
    int col0 = blockIdx.x * 128;

    float acc[32];
#pragma unroll
    for (int i = 0; i < 32; i++) acc[i] = 0.f;

    __half* sAf = (__half*)(smem + OFF_AF);
    __half* sBf = (__half*)(smem + OFF_BF);

    const int segbase[3] = {0, 512, 768};
    for (int c = 0; c < NCHUNK; c++) {
        const float* src;
        int kcol;
        if (ACCUM) { src = g_attnres; kcol = 256 + c * 64; }
        else {
            int seg = c >> 2;
            src = (seg == 0) ? token : (seg == 1) ? query : h0;
            kcol = segbase[seg] + (c & 3) * 64;
        }
        int kkb = (c & 3) * 64;
        for (int g = tid; g < 512; g += 256) {
            int m = g >> 3, kg = g & 7;
            *(uint4*)&sAf[m * STR + kg * 8] =
                cvt8(src + (size_t)(row0 + m) * Dm + kkb + kg * 8);
        }
        for (int g = tid; g < 1024; g += 256) {
            int n = g >> 3, kg = g & 7;
            size_t gi = (size_t)(col0 + n) * 1024 + kcol + kg * 8;
            *(uint4*)&sBf[n * STR + kg * 8] = *(const uint4*)&g_Gf[gi];
        }
        __syncthreads();
        mma_chunk1<2, 4>(sb + OFF_AF, sb + OFF_BF, STR * 2, wm, wn, lane, acc);
        __syncthreads();
    }

#pragma unroll
    for (int mt = 0; mt < 2; mt++)
#pragma unroll
        for (int nt = 0; nt < 4; nt++) {
            float* a4 = &acc[(mt * 4 + nt) * 4];
            int r = row0 + wm + mt * 16 + (lane >> 2);
            int cg = col0 + wn + nt * 8 + (lane & 3) * 2;
            float* p0 = &g_gates[(size_t)r * 1024 + cg];
            float* p1 = &g_gates[(size_t)(r + 8) * 1024 + cg];
            if (ACCUM) {
                float2 o0 = *(float2*)p0, o1 = *(float2*)p1;
                *(float2*)p0 = make_float2(o0.x + a4[0], o0.y + a4[1]);
                *(float2*)p1 = make_float2(o1.x + a4[2], o1.y + a4[3]);
            } else {
                *(float2*)p0 = make_float2(a4[0], a4[1]);
                *(float2*)p1 = make_float2(a4[2], a4[3]);
            }
        }
}

__global__ __launch_bounds__(256) void k_gates768(
    const float* __restrict__ token, const float* __restrict__ query,
    const float* __restrict__ h0)
{
    gates_core<12, false>(token, query, h0, threadIdx.x);
}
__global__ __launch_bounds__(256) void k_gates256()
{
    gates_core<4, true>(nullptr, nullptr, nullptr, threadIdx.x);
}

// =====================================================================
// K5: LSTM elementwise + output writes
// =====================================================================
__global__ __launch_bounds__(256) void k_lstm_ew(
    const float* __restrict__ c0, float* __restrict__ out, int write3)
{
    int n = blockIdx.x;
    int d = threadIdx.x;
    size_t g = (size_t)n * 1024;
    float gi = g_gates[g + d];
    float gf = g_gates[g + 256 + d];
    float gg = g_gates[g + 512 + d];
    float go = g_gates[g + 768 + d];
    float cprev = c0[(size_t)n * Dm + d];
    float cnew = sigm(gf) * cprev + sigm(gi) * tanh_fast(gg);
    float hnew = sigm(go) * tanh_fast(cnew);
    size_t idx = (size_t)n * Dm + d;
    out[idx] = hnew;
    if (write3) {
        out[(size_t)Nn * Dm + idx]     = hnew;
        out[(size_t)2 * Nn * Dm + idx] = cnew;
    }
}

// ---------------- streams/events (static init, outside capture) ----------
static cudaStream_t g_s1 = nullptr;
static cudaEvent_t g_e0 = nullptr, g_e_proj = nullptr, g_e_g768 = nullptr;
static bool g_streams_ok = false;
static struct StreamInit {
    StreamInit() {
        bool ok = true;
        ok &= (cudaStreamCreateWithFlags(&g_s1, cudaStreamNonBlocking) == cudaSuccess);
        ok &= (cudaEventCreateWithFlags(&g_e0, cudaEventDisableTiming) == cudaSuccess);
        ok &= (cudaEventCreateWithFlags(&g_e_proj, cudaEventDisableTiming) == cudaSuccess);
        ok &= (cudaEventCreateWithFlags(&g_e_g768, cudaEventDisableTiming) == cudaSuccess);
        g_streams_ok = ok;
    }
} g_stream_init;

// =====================================================================
// launch
// =====================================================================
extern "C" void kernel_launch(void* const* d_in, const int* in_sizes, int n_in,
                              void* d_out, int out_size)
{
    const float* token  = (const float*)d_in[0];
    const float* h0     = (const float*)d_in[1];
    const float* c0     = (const float*)d_in[2];
    const float* query  = (const float*)d_in[3];
    const float* rp     = (const float*)d_in[4];
    const float* ehs    = (const float*)d_in[5];
    const float* Wvalue = (const float*)d_in[8];
    const float* bvalue = (const float*)d_in[9];
    const float* Woff   = (const float*)d_in[10];
    const float* boff   = (const float*)d_in[11];
    const float* Waw    = (const float*)d_in[12];
    const float* baw    = (const float*)d_in[13];
    const float* Wctx   = (const float*)d_in[14];
    const float* bctx   = (const float*)d_in[15];
    const float* Whs    = (const float*)d_in[16];
    const float* bhs    = (const float*)d_in[17];
    const float* Walpha = (const float*)d_in[18];
    const float* Wih    = (const float*)d_in[20];
    const float* Whh    = (const float*)d_in[21];
    float* out = (float*)d_out;

    cudaFuncSetAttribute(k_value_mma,
                         cudaFuncAttributeMaxDynamicSharedMemorySize, V_SMEM);
    cudaFuncSetAttribute(k_proj_mma,
                         cudaFuncAttributeMaxDynamicSharedMemorySize, GEMM_SMEM);
    cudaFuncSetAttribute(k_sample_attn,
                         cudaFuncAttributeMaxDynamicSharedMemorySize, S3_SMEM);
    cudaFuncSetAttribute(k_gates768,
                         cudaFuncAttributeMaxDynamicSharedMemorySize, GEMM_SMEM);
    cudaFuncSetAttribute(k_gates256,
                         cudaFuncAttributeMaxDynamicSharedMemorySize, GEMM_SMEM);

    int write3 = (out_size >= 3 * Nn * Dm) ? 1 : 0;
    const int PREP_REST_BLOCKS = (1048576 + 8192 + 262144 + 255) / 256;  // 5152

    if (g_streams_ok) {
        k_prep_B<<<256, 256>>>(Wvalue);
        cudaEventRecord(g_e0, 0);
        cudaStreamWaitEvent(g_s1, g_e0, 0);
        k_prep_rest<<<PREP_REST_BLOCKS, 256, 0, g_s1>>>(Wih, Whh, Wctx, Woff, Waw, Whs);
        k_proj_mma<<<dim3(4, 50), 256, GEMM_SMEM, g_s1>>>(h0, query, boff, baw, bhs, bctx);
        cudaEventRecord(g_e_proj, g_s1);
        k_gates768<<<dim3(8, 50), 256, GEMM_SMEM, g_s1>>>(token, query, h0);
        cudaEventRecord(g_e_g768, g_s1);
        k_value_mma<<<1920, 256, V_SMEM>>>(ehs, bvalue);
        cudaStreamWaitEvent(0, g_e_proj, 0);
        k_sample_attn<<<Nn, 256, S3_SMEM>>>(rp, Walpha);
        cudaStreamWaitEvent(0, g_e_g768, 0);
        k_gates256<<<dim3(8, 50), 256, GEMM_SMEM>>>();
        k_lstm_ew<<<Nn, 256>>>(c0, out, write3);
    } else {
        k_prep_B<<<256, 256>>>(Wvalue);
        k_prep_rest<<<PREP_REST_BLOCKS, 256>>>(Wih, Whh, Wctx, Woff, Waw, Whs);
        k_proj_mma<<<dim3(4, 50), 256, GEMM_SMEM>>>(h0, query, boff, baw, bhs, bctx);
        k_gates768<<<dim3(8, 50), 256, GEMM_SMEM>>>(token, query, h0);
        k_value_mma<<<1920, 256, V_SMEM>>>(ehs, bvalue);
        k_sample_attn<<<Nn, 256, S3_SMEM>>>(rp, Walpha);
        k_gates256<<<dim3(8, 50), 256, GEMM_SMEM>>>();
        k_lstm_ew<<<Nn, 256>>>(c0, out, write3);
    }
}

// round 14
// speedup vs baseline: 1.1899x; 1.0710x over previous
#include <cuda_runtime.h>
#include <cuda_fp16.h>
#include <cstdint>

// ---------------- problem constants ----------------
#define Dm 256
#define Hh 8
#define HD 32
#define Ll 4
#define Pp 4
#define Bb 32
#define NQ 100
#define Nn (Bb*NQ)          // 3200
#define T_TOTAL 3840
#define LP 16
#define HLP 128

// ---------------- device scratch ----------------
__device__ __half g_value_h[(size_t)Bb * T_TOTAL * Dm];   // ~63MB (fp16)
__device__ float g_off[Nn * HLP];
__device__ float g_awl[Nn * HLP];
__device__ float g_hsproj[Nn * Dm];
__device__ __half g_ARf[Nn * Dm];          // attnres fp16
__device__ float g_gates[Nn * 4 * Dm];
__device__ __half g_Xf[(size_t)Nn * 768];  // [token|query|h0] fp16
// weights: single fp16
__device__ __half g_Bf[Dm * Dm];        // W_value^T [n][k]
__device__ __half g_Gf[1024 * 1024];    // [Wih|Whh] [j][k]
__device__ __half g_Cf[256 * 32];       // Wctx^T [e][d]
__device__ __half g_Pf[512 * 512];      // proj B [n][k]

__device__ __forceinline__ float tanh_fast(float x) {
    float e = __expf(2.0f * x);
    return 1.0f - 2.0f / (e + 1.0f);
}
__device__ __forceinline__ float tanha(float x) {
    float y;
    asm("tanh.approx.f32 %0, %1;" : "=f"(y) : "f"(x));
    return y;
}
__device__ __forceinline__ float sigm(float x) {
    return 1.0f / (1.0f + __expf(-x));
}
__device__ __forceinline__ uint32_t smem_u32(const void* p) {
    uint32_t a;
    asm("{ .reg .u64 t; cvta.to.shared.u64 t, %1; cvt.u32.u64 %0, t; }"
        : "=r"(a) : "l"(p));
    return a;
}

// ---------------- mma.sync / ldmatrix (fp16) ----------------
__device__ __forceinline__ void ldm_x4(uint32_t* r, uint32_t addr) {
    asm volatile("ldmatrix.sync.aligned.m8n8.x4.shared.b16 {%0,%1,%2,%3}, [%4];"
        : "=r"(r[0]), "=r"(r[1]), "=r"(r[2]), "=r"(r[3]) : "r"(addr));
}
#define MMAH(d, a, b) \
    asm volatile("mma.sync.aligned.m16n8k16.row.col.f32.f16.f16.f32 " \
        "{%0,%1,%2,%3}, {%4,%5,%6,%7}, {%8,%9}, {%0,%1,%2,%3};" \
        : "+f"((d)[0]), "+f"((d)[1]), "+f"((d)[2]), "+f"((d)[3]) \
        : "r"((a)[0]), "r"((a)[1]), "r"((a)[2]), "r"((a)[3]), \
          "r"((b)[0]), "r"((b)[1]))

// single-term chunk: A x B, both fp16. warp tile 32m x (NT2*16)n
template<int NT2, int KS>
__device__ __forceinline__ void mma_chunk1(
    uint32_t aF, uint32_t bF,
    uint32_t stride2, int wm, int wn, int lane, float* acc)
{
    int arow = lane & 15, acol8 = (lane >> 4) * 8;
    int brow = ((lane >> 4) & 1) * 8 + (lane & 7);
    int bcol8 = ((lane >> 3) & 1) * 8;
#pragma unroll
    for (int ks = 0; ks < KS; ks++) {
        uint32_t Af[2][4], B[NT2][4];
#pragma unroll
        for (int mt = 0; mt < 2; mt++) {
            uint32_t off = (uint32_t)(wm + mt * 16 + arow) * stride2
                         + (uint32_t)(ks * 16 + acol8) * 2;
            ldm_x4(Af[mt], aF + off);
        }
#pragma unroll
        for (int nt2 = 0; nt2 < NT2; nt2++) {
            uint32_t off = (uint32_t)(wn + nt2 * 16 + brow) * stride2
                         + (uint32_t)(ks * 16 + bcol8) * 2;
            ldm_x4(B[nt2], bF + off);
        }
#pragma unroll
        for (int mt = 0; mt < 2; mt++)
#pragma unroll
            for (int nt = 0; nt < 2 * NT2; nt++)
                MMAH(acc + (mt * 2 * NT2 + nt) * 4, Af[mt],
                     (&B[nt >> 1][(nt & 1) * 2]));
    }
}

#define STR 72
// generic GEMM smem (BM=64, BN=128): A 9216, B 18432
#define OFF_AF 0
#define OFF_BF 9216
#define GEMM_SMEM 27648
// value: A 9216, B 36864
#define V_AF 0
#define V_BF 9216
#define V_SMEM 46080

// fp32 row staging: convert 8 floats -> 8 halves -> uint4
__device__ __forceinline__ uint4 cvt8(const float* s) {
    float4 v0 = *(const float4*)s;
    float4 v1 = *(const float4*)(s + 4);
    __half hh[8];
    hh[0] = __float2half_rn(v0.x); hh[1] = __float2half_rn(v0.y);
    hh[2] = __float2half_rn(v0.z); hh[3] = __float2half_rn(v0.w);
    hh[4] = __float2half_rn(v1.x); hh[5] = __float2half_rn(v1.y);
    hh[6] = __float2half_rn(v1.z); hh[7] = __float2half_rn(v1.w);
    return *(uint4*)hh;
}

// =====================================================================
// K0a: prep W_value -> fp16 (transposed)
// =====================================================================
__global__ __launch_bounds__(256) void k_prep_B(const float* __restrict__ Wvalue)
{
    int idx = blockIdx.x * 256 + threadIdx.x;   // < 65536
    int n = idx >> 8, k = idx & 255;
    g_Bf[idx] = __float2half_rn(Wvalue[k * Dm + n]);
}

// =====================================================================
// K0c: prep activations -> fp16 [token|query|h0] per row
// =====================================================================
__global__ __launch_bounds__(256) void k_prep_x(
    const float* __restrict__ token, const float* __restrict__ query,
    const float* __restrict__ h0)
{
    int idx = blockIdx.x * 256 + threadIdx.x;   // < 3200*768
    int n = idx / 768, col = idx - n * 768;
    float v;
    if (col < 256)      v = token[n * 256 + col];
    else if (col < 512) v = query[n * 256 + (col - 256)];
    else                v = h0[n * 256 + (col - 512)];
    g_Xf[idx] = __float2half_rn(v);
}

// =====================================================================
// K0b: prep remaining weights -> fp16
// =====================================================================
__global__ __launch_bounds__(256) void k_prep_rest(
    const float* __restrict__ Wih, const float* __restrict__ Whh,
    const float* __restrict__ Wctx,
    const float* __restrict__ Woff, const float* __restrict__ Waw,
    const float* __restrict__ Whs)
{
    int idx = blockIdx.x * 256 + threadIdx.x;
    if (idx < 1048576) {
        int j = idx >> 10, k = idx & 1023;
        float v = (k < 768) ? Wih[(size_t)j * 768 + k]
                            : Whh[(size_t)j * 256 + (k - 768)];
        g_Gf[idx] = __float2half_rn(v);
    } else if (idx < 1048576 + 8192) {
        int i = idx - 1048576;
        int e = i >> 5, k = i & 31;
        g_Cf[i] = __float2half_rn(Wctx[k * 256 + e]);
    } else if (idx < 1056768 + 262144) {
        int i = idx - 1056768;
        int n = i >> 9, k = i & 511;
        float v;
        if (n < 128)      v = Woff[k * 128 + n];
        else if (n < 256) v = Waw[k * 128 + (n - 128)];
        else              v = (k < 256) ? Whs[k * 256 + (n - 256)] : 0.f;
        g_Pf[i] = __float2half_rn(v);
    }
}

// =====================================================================
// K1: value GEMM (fp16 1-term, fp16 output). grid 1920, BM=64, BN=256
// =====================================================================
__global__ __launch_bounds__(256, 2) void k_value_mma(
    const float* __restrict__ A, const float* __restrict__ bias)
{
    extern __shared__ char smem[];
    uint32_t sb = smem_u32(smem);
    int tid = threadIdx.x;
    int w = tid >> 5, lane = tid & 31;
    int wm = (w >> 2) * 32, wn = (w & 3) * 64;
    int row0 = blockIdx.x * 64;

    float acc[64];
#pragma unroll
    for (int i = 0; i < 64; i++) acc[i] = 0.f;

    __half* sAf = (__half*)(smem + V_AF);
    __half* sBf = (__half*)(smem + V_BF);

    uint4 pfA[2];
    auto ldA = [&](int c) {
#pragma unroll
        for (int i = 0; i < 2; i++) {
            int g = tid + i * 256;
            int m = g >> 3, kg = g & 7;
            pfA[i] = cvt8(A + (size_t)(row0 + m) * Dm + c * 64 + kg * 8);
        }
    };
    auto stsA = [&]() {
#pragma unroll
        for (int i = 0; i < 2; i++) {
            int g = tid + i * 256;
            int m = g >> 3, kg = g & 7;
            *(uint4*)&sAf[m * STR + kg * 8] = pfA[i];
        }
    };

    ldA(0);
    for (int c = 0; c < 4; c++) {
        stsA();
        for (int g = tid; g < 2048; g += 256) {
            int n = g >> 3, kg = g & 7;
            int gi = n * Dm + c * 64 + kg * 8;
            *(uint4*)&sBf[n * STR + kg * 8] = *(const uint4*)&g_Bf[gi];
        }
        __syncthreads();
        if (c < 3) ldA(c + 1);
        mma_chunk1<4, 4>(sb + V_AF, sb + V_BF, STR * 2, wm, wn, lane, acc);
        __syncthreads();
    }

#pragma unroll
    for (int mt = 0; mt < 2; mt++)
#pragma unroll
        for (int nt = 0; nt < 8; nt++) {
            float* a4 = &acc[(mt * 8 + nt) * 4];
            int r = row0 + wm + mt * 16 + (lane >> 2);
            int cg = wn + nt * 8 + (lane & 3) * 2;
            float b0 = __ldg(&bias[cg]), b1 = __ldg(&bias[cg + 1]);
            *(__half2*)&g_value_h[(size_t)r * Dm + cg] =
                __floats2half2_rn(a4[0] + b0, a4[1] + b1);
            *(__half2*)&g_value_h[(size_t)(r + 8) * Dm + cg] =
                __floats2half2_rn(a4[2] + b0, a4[3] + b1);
        }
}

// =====================================================================
// K2: proj GEMM, BM=64 x BN=128. grid (4,50). A from g_Xf (fp16)
// =====================================================================
__global__ __launch_bounds__(256) void k_proj_mma(
    const float* __restrict__ boff, const float* __restrict__ baw,
    const float* __restrict__ bhs,  const float* __restrict__ bctx)
{
    extern __shared__ char smem[];
    uint32_t sb = smem_u32(smem);
    int tid = threadIdx.x;
    int w = tid >> 5, lane = tid & 31;
    int wm = (w >> 2) * 32, wn = (w & 3) * 32;
    int row0 = blockIdx.y * 64;
    int col0 = blockIdx.x * 128;

    float acc[32];
#pragma unroll
    for (int i = 0; i < 32; i++) acc[i] = 0.f;

    __half* sAf = (__half*)(smem + OFF_AF);
    __half* sBf = (__half*)(smem + OFF_BF);

    uint4 pfA[2];
    // proj A col mapping: c<4 -> h0 (Xf col 512+), c>=4 -> query (Xf col 256+)
    auto ldA = [&](int c) {
        int xcol = (c < 4) ? (512 + c * 64) : (256 + (c - 4) * 64);
#pragma unroll
        for (int i = 0; i < 2; i++) {
            int g = tid + i * 256;
            int m = g >> 3, kg = g & 7;
            pfA[i] = *(const uint4*)&g_Xf[(size_t)(row0 + m) * 768 + xcol + kg * 8];
        }
    };
    auto stsA = [&]() {
#pragma unroll
        for (int i = 0; i < 2; i++) {
            int g = tid + i * 256;
            int m = g >> 3, kg = g & 7;
            *(uint4*)&sAf[m * STR + kg * 8] = pfA[i];
        }
    };

    ldA(0);
    for (int c = 0; c < 8; c++) {
        stsA();
        for (int g = tid; g < 1024; g += 256) {
            int n = g >> 3, kg = g & 7;
            int gi = (col0 + n) * 512 + c * 64 + kg * 8;
            *(uint4*)&sBf[n * STR + kg * 8] = *(const uint4*)&g_Pf[gi];
        }
        __syncthreads();
        if (c < 7) ldA(c + 1);
        mma_chunk1<2, 4>(sb + OFF_AF, sb + OFF_BF, STR * 2, wm, wn, lane, acc);
        __syncthreads();
    }

    int bx = blockIdx.x;
#pragma unroll
    for (int mt = 0; mt < 2; mt++)
#pragma unroll
        for (int nt = 0; nt < 4; nt++) {
            float* a4 = &acc[(mt * 4 + nt) * 4];
            int r = row0 + wm + mt * 16 + (lane >> 2);
            int cl = wn + nt * 8 + (lane & 3) * 2;
            if (bx == 0) {
                float b0 = __ldg(&boff[cl]), b1 = __ldg(&boff[cl + 1]);
                *(float2*)&g_off[r * 128 + cl] = make_float2(a4[0] + b0, a4[1] + b1);
                *(float2*)&g_off[(r + 8) * 128 + cl] = make_float2(a4[2] + b0, a4[3] + b1);
            } else if (bx == 1) {
                float b0 = __ldg(&baw[cl]), b1 = __ldg(&baw[cl + 1]);
                *(float2*)&g_awl[r * 128 + cl] = make_float2(a4[0] + b0, a4[1] + b1);
                *(float2*)&g_awl[(r + 8) * 128 + cl] = make_float2(a4[2] + b0, a4[3] + b1);
            } else {
                int col = (bx - 2) * 128 + cl;
                float b0 = __ldg(&bhs[col]) + __ldg(&bctx[col]);
                float b1 = __ldg(&bhs[col + 1]) + __ldg(&bctx[col + 1]);
                *(float2*)&g_hsproj[r * 256 + col] = make_float2(a4[0] + b0, a4[1] + b1);
                *(float2*)&g_hsproj[(r + 8) * 256 + col] = make_float2(a4[2] + b0, a4[3] + b1);
            }
        }
}

// =====================================================================
// K3: sample + additive attention (fp16 value in, fp16 attnres out)
// =====================================================================
#define A3STR 40
#define S3_AF  0
#define S3_BF  10240
#define S3_ADD 30720
#define S3_WA  31744
#define S3_AW  32768
#define S3_SC  33280
#define S3_SMEM 33792

__global__ __launch_bounds__(256) void k_sample_attn(
    const float* __restrict__ rp,
    const float* __restrict__ Walpha)
{
    extern __shared__ char sm3[];
    __half* sAf3 = (__half*)(sm3 + S3_AF);
    __half* sBf3 = (__half*)(sm3 + S3_BF);
    float* add_s = (float*)(sm3 + S3_ADD);
    float* Wa_s  = (float*)(sm3 + S3_WA);
    float* aw_s  = (float*)(sm3 + S3_AW);
    float* sc_s  = (float*)(sm3 + S3_SC);

    int n = blockIdx.x;
    int tid = threadIdx.x;
    int w = tid >> 5, lane = tid & 31;
    int b = n / NQ;

    for (int g = tid; g < 1024; g += 256) {
        int r = g >> 2, kg = (g & 3) * 8;
        *(uint4*)&sBf3[r * A3STR + kg] = *(const uint4*)&g_Cf[r * 32 + kg];
    }
    if (tid < 128) { aw_s[tid] = g_awl[n * 128 + tid]; sc_s[tid] = 0.f; }
    add_s[tid] = g_hsproj[n * 256 + tid];
    Wa_s[tid] = Walpha[tid];
    __syncthreads();

    if (lane < 16) {
        float v = aw_s[w * 16 + lane];
        float mx = v;
#pragma unroll
        for (int o = 8; o > 0; o >>= 1)
            mx = fmaxf(mx, __shfl_xor_sync(0x0000ffffu, mx, o, 16));
        float ev = __expf(v - mx);
        float s = ev;
#pragma unroll
        for (int o = 8; o > 0; o >>= 1)
            s += __shfl_xor_sync(0x0000ffffu, s, o, 16);
        aw_s[w * 16 + lane] = ev / s;
    }
    __syncthreads();

    {
        const int TLS[4]    = {2048, 1024, 512, 256};
        const int STARTS[4] = {0, 2048, 3072, 3584};
        int pair = tid >> 1, half = tid & 1;
        int h2 = pair >> 4, lp = pair & 15, l = lp >> 2;
        int Tl = TLS[l], st = STARTS[l];
        float ref = rp[n * Ll + l];
        float off = g_off[n * HLP + pair];
        float aw = aw_s[pair];
        float x = ref * (float)Tl + off - 0.5f;
        float xf = floorf(x);
        float w1 = x - xf, w0 = 1.0f - w1;
        int i0 = (int)xf, i1 = i0 + 1;
        float wa0 = aw * w0 * ((i0 >= 0 && i0 < Tl) ? 1.f : 0.f);
        float wa1 = aw * w1 * ((i1 >= 0 && i1 < Tl) ? 1.f : 0.f);
        int c0i = min(max(i0, 0), Tl - 1);
        int c1i = min(max(i1, 0), Tl - 1);
        size_t base0 = ((size_t)(b * T_TOTAL + st + c0i)) * Dm + h2 * HD + half * 16;
        size_t base1 = ((size_t)(b * T_TOTAL + st + c1i)) * Dm + h2 * HD + half * 16;
        uint4 ua[2], ub[2];
        ua[0] = *(const uint4*)&g_value_h[base0];
        ua[1] = *(const uint4*)&g_value_h[base0 + 8];
        ub[0] = *(const uint4*)&g_value_h[base1];
        ub[1] = *(const uint4*)&g_value_h[base1 + 8];
        const __half2* ha = (const __half2*)ua;
        const __half2* hb = (const __half2*)ub;
        uint4 outv[2];
        __half2* ho = (__half2*)outv;
#pragma unroll
        for (int q2 = 0; q2 < 8; q2++) {
            float2 fa = __half22float2(ha[q2]);
            float2 fb = __half22float2(hb[q2]);
            ho[q2] = __floats2half2_rn(wa0 * fa.x + wa1 * fb.x,
                                       wa0 * fa.y + wa1 * fb.y);
        }
        int d = half * 16;
        *(uint4*)&sAf3[pair * A3STR + d]     = outv[0];
        *(uint4*)&sAf3[pair * A3STR + d + 8] = outv[1];
    }
    __syncthreads();

    uint32_t aF = smem_u32(sAf3);
    uint32_t bF = smem_u32(sBf3);
    int wm = (w >> 1) * 32, wnl = (w & 1) * 32;
    float scoreacc[2][2] = {{0.f, 0.f}, {0.f, 0.f}};

#pragma unroll
    for (int pass = 0; pass < 4; pass++) {
        uint32_t boff2 = (uint32_t)(pass * 64 * A3STR * 2);
        float acc[32];
#pragma unroll
        for (int i = 0; i < 32; i++) acc[i] = 0.f;
        mma_chunk1<2, 2>(aF, bF + boff2, A3STR * 2, wm, wnl, lane, acc);
#pragma unroll
        for (int mt = 0; mt < 2; mt++)
#pragma unroll
            for (int nt = 0; nt < 4; nt++) {
                float* a4 = &acc[(mt * 4 + nt) * 4];
                int e0 = pass * 64 + wnl + nt * 8 + (lane & 3) * 2;
                scoreacc[mt][0] += tanha(a4[0] + add_s[e0]) * Wa_s[e0];
                scoreacc[mt][0] += tanha(a4[1] + add_s[e0 + 1]) * Wa_s[e0 + 1];
                scoreacc[mt][1] += tanha(a4[2] + add_s[e0]) * Wa_s[e0];
                scoreacc[mt][1] += tanha(a4[3] + add_s[e0 + 1]) * Wa_s[e0 + 1];
            }
    }

#pragma unroll
    for (int mt = 0; mt < 2; mt++) {
        float s0 = scoreacc[mt][0], s1 = scoreacc[mt][1];
        s0 += __shfl_xor_sync(0xffffffffu, s0, 1);
        s0 += __shfl_xor_sync(0xffffffffu, s0, 2);
        s1 += __shfl_xor_sync(0xffffffffu, s1, 1);
        s1 += __shfl_xor_sync(0xffffffffu, s1, 2);
        if ((lane & 3) == 0) {
            atomicAdd(&sc_s[wm + mt * 16 + (lane >> 2)], s0);
            atomicAdd(&sc_s[wm + mt * 16 + 8 + (lane >> 2)], s1);
        }
    }
    __syncthreads();

    if (lane < 16) {
        float v = sc_s[w * 16 + lane];
        float mx = v;
#pragma unroll
        for (int o = 8; o > 0; o >>= 1)
            mx = fmaxf(mx, __shfl_xor_sync(0x0000ffffu, mx, o, 16));
        float ev = __expf(v - mx);
        float s = ev;
#pragma unroll
        for (int o = 8; o > 0; o >>= 1)
            s += __shfl_xor_sync(0x0000ffffu, s, o, 16);
        sc_s[w * 16 + lane] = ev / s;
    }
    __syncwarp();

    {
        float accw = 0.f;
#pragma unroll
        for (int p = 0; p < 16; p++) {
            int r = (w * 16 + p) * A3STR + lane;
            accw += sc_s[w * 16 + p] * __half2float(sAf3[r]);
        }
        g_ARf[(size_t)n * Dm + w * HD + lane] = __float2half_rn(accw);
    }
}

// =====================================================================
// K4a/K4b: gates GEMMs, BM=64 x BN=128, A from fp16 arrays + prefetch
// =====================================================================
template<int NCHUNK, bool ACCUM>
__device__ __forceinline__ void gates_core(int tid)
{
    extern __shared__ char smem[];
    uint32_t sb = smem_u32(smem);
    int w = tid >> 5, lane = tid & 31;
    int wm = (w >> 2) * 32, wn = (w & 3) * 32;
    int row0 = blockIdx.y * 64;
    int col0 = blockIdx.x * 128;

    float acc[32];
#pragma unroll
    for (int i = 0; i < 32; i++) acc[i] = 0.f;

    __half* sAf = (__half*)(smem + OFF_AF);
    __half* sBf = (__half*)(smem + OFF_BF);

    uint4 pfA[2];
    auto ldA = [&](int c) {
#pragma unroll
        for (int i = 0; i < 2; i++) {
            int g = tid + i * 256;
            int m = g >> 3, kg = g & 7;
            if (ACCUM)
                pfA[i] = *(const uint4*)&g_ARf[(size_t)(row0 + m) * 256 + c * 64 + kg * 8];
            else
                pfA[i] = *(const uint4*)&g_Xf[(size_t)(row0 + m) * 768 + c * 64 + kg * 8];
        }
    };
    auto stsA = [&]() {
#pragma unroll
        for (int i = 0; i < 2; i++) {
            int g = tid + i * 256;
            int m = g >> 3, kg = g & 7;
            *(uint4*)&sAf[m * STR + kg * 8] = pfA[i];
        }
    };

    // weight column mapping: Xf seg order token(0)/query(1)/h0(2) ->
    // W cols token 0-255, query 512-767, h0 768-1023; attnres 256-511
    ldA(0);
    for (int c = 0; c < NCHUNK; c++) {
        int kcol;
        if (ACCUM) kcol = 256 + c * 64;
        else {
            int seg = c >> 2;
            kcol = ((seg == 0) ? 0 : (seg == 1) ? 512 : 768) + (c & 3) * 64;
        }
        stsA();
        for (int g = tid; g < 1024; g += 256) {
            int n = g >> 3, kg = g & 7;
            size_t gi = (size_t)(col0 + n) * 1024 + kcol + kg * 8;
            *(uint4*)&sBf[n * STR + kg * 8] = *(const uint4*)&g_Gf[gi];
        }
        __syncthreads();
        if (c < NCHUNK - 1) ldA(c + 1);
        mma_chunk1<2, 4>(sb + OFF_AF, sb + OFF_BF, STR * 2, wm, wn, lane, acc);
        __syncthreads();
    }

#pragma unroll
    for (int mt = 0; mt < 2; mt++)
#pragma unroll
        for (int nt = 0; nt < 4; nt++) {
            float* a4 = &acc[(mt * 4 + nt) * 4];
            int r = row0 + wm + mt * 16 + (lane >> 2);
            int cg = col0 + wn + nt * 8 + (lane & 3) * 2;
            float* p0 = &g_gates[(size_t)r * 1024 + cg];
            float* p1 = &g_gates[(size_t)(r + 8) * 1024 + cg];
            if (ACCUM) {
                float2 o0 = *(float2*)p0, o1 = *(float2*)p1;
                *(float2*)p0 = make_float2(o0.x + a4[0], o0.y + a4[1]);
                *(float2*)p1 = make_float2(o1.x + a4[2], o1.y + a4[3]);
            } else {
                *(float2*)p0 = make_float2(a4[0], a4[1]);
                *(float2*)p1 = make_float2(a4[2], a4[3]);
            }
        }
}

__global__ __launch_bounds__(256) void k_gates768()
{
    gates_core<12, false>(threadIdx.x);
}
__global__ __launch_bounds__(256) void k_gates256()
{
    gates_core<4, true>(threadIdx.x);
}

// =====================================================================
// K5: LSTM elementwise + output writes
// =====================================================================
__global__ __launch_bounds__(256) void k_lstm_ew(
    const float* __restrict__ c0, float* __restrict__ out, int write3)
{
    int n = blockIdx.x;
    int d = threadIdx.x;
    size_t g = (size_t)n * 1024;
    float gi = g_gates[g + d];
    float gf = g_gates[g + 256 + d];
    float gg = g_gates[g + 512 + d];
    float go = g_gates[g + 768 + d];
    float cprev = c0[(size_t)n * Dm + d];
    float cnew = sigm(gf) * cprev + sigm(gi) * tanh_fast(gg);
    float hnew = sigm(go) * tanh_fast(cnew);
    size_t idx = (size_t)n * Dm + d;
    out[idx] = hnew;
    if (write3) {
        out[(size_t)Nn * Dm + idx]     = hnew;
        out[(size_t)2 * Nn * Dm + idx] = cnew;
    }
}

// ---------------- streams/events (static init, outside capture) ----------
static cudaStream_t g_s1 = nullptr;
static cudaEvent_t g_e0 = nullptr, g_e_proj = nullptr, g_e_g768 = nullptr;
static bool g_streams_ok = false;
static struct StreamInit {
    StreamInit() {
        bool ok = true;
        ok &= (cudaStreamCreateWithFlags(&g_s1, cudaStreamNonBlocking) == cudaSuccess);
        ok &= (cudaEventCreateWithFlags(&g_e0, cudaEventDisableTiming) == cudaSuccess);
        ok &= (cudaEventCreateWithFlags(&g_e_proj, cudaEventDisableTiming) == cudaSuccess);
        ok &= (cudaEventCreateWithFlags(&g_e_g768, cudaEventDisableTiming) == cudaSuccess);
        g_streams_ok = ok;
    }
} g_stream_init;

// =====================================================================
// launch
// =====================================================================
extern "C" void kernel_launch(void* const* d_in, const int* in_sizes, int n_in,
                              void* d_out, int out_size)
{
    const float* token  = (const float*)d_in[0];
    const float* h0     = (const float*)d_in[1];
    const float* c0     = (const float*)d_in[2];
    const float* query  = (const float*)d_in[3];
    const float* rp     = (const float*)d_in[4];
    const float* ehs    = (const float*)d_in[5];
    const float* Wvalue = (const float*)d_in[8];
    const float* bvalue = (const float*)d_in[9];
    const float* Woff   = (const float*)d_in[10];
    const float* boff   = (const float*)d_in[11];
    const float* Waw    = (const float*)d_in[12];
    const float* baw    = (const float*)d_in[13];
    const float* Wctx   = (const float*)d_in[14];
    const float* bctx   = (const float*)d_in[15];
    const float* Whs    = (const float*)d_in[16];
    const float* bhs    = (const float*)d_in[17];
    const float* Walpha = (const float*)d_in[18];
    const float* Wih    = (const float*)d_in[20];
    const float* Whh    = (const float*)d_in[21];
    float* out = (float*)d_out;

    cudaFuncSetAttribute(k_value_mma,
                         cudaFuncAttributeMaxDynamicSharedMemorySize, V_SMEM);
    cudaFuncSetAttribute(k_proj_mma,
                         cudaFuncAttributeMaxDynamicSharedMemorySize, GEMM_SMEM);
    cudaFuncSetAttribute(k_sample_attn,
                         cudaFuncAttributeMaxDynamicSharedMemorySize, S3_SMEM);
    cudaFuncSetAttribute(k_gates768,
                         cudaFuncAttributeMaxDynamicSharedMemorySize, GEMM_SMEM);
    cudaFuncSetAttribute(k_gates256,
                         cudaFuncAttributeMaxDynamicSharedMemorySize, GEMM_SMEM);

    int write3 = (out_size >= 3 * Nn * Dm) ? 1 : 0;
    const int PREP_REST_BLOCKS = (1048576 + 8192 + 262144 + 255) / 256;  // 5152
    const int PREP_X_BLOCKS = (Nn * 768 + 255) / 256;                    // 9600

    if (g_streams_ok) {
        k_prep_B<<<256, 256>>>(Wvalue);
        cudaEventRecord(g_e0, 0);
        // side branch: activation prep, weight prep, proj, gates768
        k_prep_x<<<PREP_X_BLOCKS, 256, 0, g_s1>>>(token, query, h0);
        cudaStreamWaitEvent(g_s1, g_e0, 0);
        k_prep_rest<<<PREP_REST_BLOCKS, 256, 0, g_s1>>>(Wih, Whh, Wctx, Woff, Waw, Whs);
        k_proj_mma<<<dim3(4, 50), 256, GEMM_SMEM, g_s1>>>(boff, baw, bhs, bctx);
        cudaEventRecord(g_e_proj, g_s1);
        k_gates768<<<dim3(8, 50), 256, GEMM_SMEM, g_s1>>>();
        cudaEventRecord(g_e_g768, g_s1);
        // main branch
        k_value_mma<<<1920, 256, V_SMEM>>>(ehs, bvalue);
        cudaStreamWaitEvent(0, g_e_proj, 0);
        k_sample_attn<<<Nn, 256, S3_SMEM>>>(rp, Walpha);
        cudaStreamWaitEvent(0, g_e_g768, 0);
        k_gates256<<<dim3(8, 50), 256, GEMM_SMEM>>>();
        k_lstm_ew<<<Nn, 256>>>(c0, out, write3);
    } else {
        k_prep_B<<<256, 256>>>(Wvalue);
        k_prep_x<<<PREP_X_BLOCKS, 256>>>(token, query, h0);
        k_prep_rest<<<PREP_REST_BLOCKS, 256>>>(Wih, Whh, Wctx, Woff, Waw, Whs);
        k_proj_mma<<<dim3(4, 50), 256, GEMM_SMEM>>>(boff, baw, bhs, bctx);
        k_gates768<<<dim3(8, 50), 256, GEMM_SMEM>>>();
        k_value_mma<<<1920, 256, V_SMEM>>>(ehs, bvalue);
        k_sample_attn<<<Nn, 256, S3_SMEM>>>(rp, Walpha);
        k_gates256<<<dim3(8, 50), 256, GEMM_SMEM>>>();
        k_lstm_ew<<<Nn, 256>>>(c0, out, write3);
    }
}

// round 15
// speedup vs baseline: 1.4985x; 1.2594x over previous
#include <cuda_runtime.h>
#include <cuda_fp16.h>
#include <cstdint>

// ---------------- problem constants ----------------
#define Dm 256
#define Hh 8
#define HD 32
#define Ll 4
#define Pp 4
#define Bb 32
#define NQ 100
#define Nn (Bb*NQ)          // 3200
#define T_TOTAL 3840
#define LP 16
#define HLP 128

// ---------------- device scratch ----------------
__device__ __half g_value_h[(size_t)Bb * T_TOTAL * Dm];   // ~63MB (fp16)
__device__ float g_off[Nn * HLP];
__device__ float g_awl[Nn * HLP];
__device__ float g_hsproj[Nn * Dm];
__device__ __half g_ARf[Nn * Dm];          // attnres fp16
__device__ float g_gates[Nn * 4 * Dm];
__device__ __half g_Xf[(size_t)Nn * 768];  // [token|query|h0] fp16
// weights: single fp16
__device__ __half g_Bf[Dm * Dm];        // W_value^T [n][k]
__device__ __half g_Gf[1024 * 1024];    // [Wih|Whh] [j][k]
__device__ __half g_Cf[256 * 32];       // Wctx^T [e][d]
__device__ __half g_Pf[512 * 512];      // proj B [n][k]

__device__ __forceinline__ float tanh_fast(float x) {
    float e = __expf(2.0f * x);
    return 1.0f - 2.0f / (e + 1.0f);
}
__device__ __forceinline__ float tanha(float x) {
    float y;
    asm("tanh.approx.f32 %0, %1;" : "=f"(y) : "f"(x));
    return y;
}
__device__ __forceinline__ float sigm(float x) {
    return 1.0f / (1.0f + __expf(-x));
}
__device__ __forceinline__ uint32_t smem_u32(const void* p) {
    uint32_t a;
    asm("{ .reg .u64 t; cvta.to.shared.u64 t, %1; cvt.u32.u64 %0, t; }"
        : "=r"(a) : "l"(p));
    return a;
}

// ---------------- cp.async ----------------
__device__ __forceinline__ void cp_async16(uint32_t dst, const void* src) {
    asm volatile("cp.async.cg.shared.global [%0], [%1], 16;"
                 :: "r"(dst), "l"(src) : "memory");
}
#define CP_COMMIT() asm volatile("cp.async.commit_group;" ::: "memory")
#define CP_WAIT1()  asm volatile("cp.async.wait_group 1;" ::: "memory")
#define CP_WAIT0()  asm volatile("cp.async.wait_group 0;" ::: "memory")

// ---------------- mma.sync / ldmatrix (fp16) ----------------
__device__ __forceinline__ void ldm_x4(uint32_t* r, uint32_t addr) {
    asm volatile("ldmatrix.sync.aligned.m8n8.x4.shared.b16 {%0,%1,%2,%3}, [%4];"
        : "=r"(r[0]), "=r"(r[1]), "=r"(r[2]), "=r"(r[3]) : "r"(addr));
}
#define MMAH(d, a, b) \
    asm volatile("mma.sync.aligned.m16n8k16.row.col.f32.f16.f16.f32 " \
        "{%0,%1,%2,%3}, {%4,%5,%6,%7}, {%8,%9}, {%0,%1,%2,%3};" \
        : "+f"((d)[0]), "+f"((d)[1]), "+f"((d)[2]), "+f"((d)[3]) \
        : "r"((a)[0]), "r"((a)[1]), "r"((a)[2]), "r"((a)[3]), \
          "r"((b)[0]), "r"((b)[1]))

// single-term chunk: A x B, both fp16. warp tile 32m x (NT2*16)n
template<int NT2, int KS>
__device__ __forceinline__ void mma_chunk1(
    uint32_t aF, uint32_t bF,
    uint32_t stride2, int wm, int wn, int lane, float* acc)
{
    int arow = lane & 15, acol8 = (lane >> 4) * 8;
    int brow = ((lane >> 4) & 1) * 8 + (lane & 7);
    int bcol8 = ((lane >> 3) & 1) * 8;
#pragma unroll
    for (int ks = 0; ks < KS; ks++) {
        uint32_t Af[2][4], B[NT2][4];
#pragma unroll
        for (int mt = 0; mt < 2; mt++) {
            uint32_t off = (uint32_t)(wm + mt * 16 + arow) * stride2
                         + (uint32_t)(ks * 16 + acol8) * 2;
            ldm_x4(Af[mt], aF + off);
        }
#pragma unroll
        for (int nt2 = 0; nt2 < NT2; nt2++) {
            uint32_t off = (uint32_t)(wn + nt2 * 16 + brow) * stride2
                         + (uint32_t)(ks * 16 + bcol8) * 2;
            ldm_x4(B[nt2], bF + off);
        }
#pragma unroll
        for (int mt = 0; mt < 2; mt++)
#pragma unroll
            for (int nt = 0; nt < 2 * NT2; nt++)
                MMAH(acc + (mt * 2 * NT2 + nt) * 4, Af[mt],
                     (&B[nt >> 1][(nt & 1) * 2]));
    }
}

#define STR 72
// generic GEMM: A 9216, B double buf 2x18432
#define OFF_AF 0
#define OFF_BF(b) (9216 + (b) * 18432)
#define GEMM_SMEM 46080
// value: A 9216, B double buf 2x36864
#define V_AF 0
#define V_BF(b) (9216 + (b) * 36864)
#define V_SMEM 82944

// fp32 row staging: convert 8 floats -> 8 halves -> uint4
__device__ __forceinline__ uint4 cvt8(const float* s) {
    float4 v0 = *(const float4*)s;
    float4 v1 = *(const float4*)(s + 4);
    __half hh[8];
    hh[0] = __float2half_rn(v0.x); hh[1] = __float2half_rn(v0.y);
    hh[2] = __float2half_rn(v0.z); hh[3] = __float2half_rn(v0.w);
    hh[4] = __float2half_rn(v1.x); hh[5] = __float2half_rn(v1.y);
    hh[6] = __float2half_rn(v1.z); hh[7] = __float2half_rn(v1.w);
    return *(uint4*)hh;
}

// =====================================================================
// K0a: prep W_value -> fp16 (transposed)
// =====================================================================
__global__ __launch_bounds__(256) void k_prep_B(const float* __restrict__ Wvalue)
{
    int idx = blockIdx.x * 256 + threadIdx.x;   // < 65536
    int n = idx >> 8, k = idx & 255;
    g_Bf[idx] = __float2half_rn(Wvalue[k * Dm + n]);
}

// =====================================================================
// K0c: prep activations -> fp16 [token|query|h0] per row
// =====================================================================
__global__ __launch_bounds__(256) void k_prep_x(
    const float* __restrict__ token, const float* __restrict__ query,
    const float* __restrict__ h0)
{
    int idx = blockIdx.x * 256 + threadIdx.x;
    int n = idx / 768, col = idx - n * 768;
    float v;
    if (col < 256)      v = token[n * 256 + col];
    else if (col < 512) v = query[n * 256 + (col - 256)];
    else                v = h0[n * 256 + (col - 512)];
    g_Xf[idx] = __float2half_rn(v);
}

// =====================================================================
// K0b: prep remaining weights -> fp16
// =====================================================================
__global__ __launch_bounds__(256) void k_prep_rest(
    const float* __restrict__ Wih, const float* __restrict__ Whh,
    const float* __restrict__ Wctx,
    const float* __restrict__ Woff, const float* __restrict__ Waw,
    const float* __restrict__ Whs)
{
    int idx = blockIdx.x * 256 + threadIdx.x;
    if (idx < 1048576) {
        int j = idx >> 10, k = idx & 1023;
        float v = (k < 768) ? Wih[(size_t)j * 768 + k]
                            : Whh[(size_t)j * 256 + (k - 768)];
        g_Gf[idx] = __float2half_rn(v);
    } else if (idx < 1048576 + 8192) {
        int i = idx - 1048576;
        int e = i >> 5, k = i & 31;
        g_Cf[i] = __float2half_rn(Wctx[k * 256 + e]);
    } else if (idx < 1056768 + 262144) {
        int i = idx - 1056768;
        int n = i >> 9, k = i & 511;
        float v;
        if (n < 128)      v = Woff[k * 128 + n];
        else if (n < 256) v = Waw[k * 128 + (n - 128)];
        else              v = (k < 256) ? Whs[k * 256 + (n - 256)] : 0.f;
        g_Pf[i] = __float2half_rn(v);
    }
}

// =====================================================================
// K1: value GEMM (fp16, cp.async double-buffered B). grid 1920, BM=64
// =====================================================================
__global__ __launch_bounds__(256, 2) void k_value_mma(
    const float* __restrict__ A, const float* __restrict__ bias)
{
    extern __shared__ char smem[];
    uint32_t sb = smem_u32(smem);
    int tid = threadIdx.x;
    int w = tid >> 5, lane = tid & 31;
    int wm = (w >> 2) * 32, wn = (w & 3) * 64;
    int row0 = blockIdx.x * 64;

    float acc[64];
#pragma unroll
    for (int i = 0; i < 64; i++) acc[i] = 0.f;

    __half* sAf = (__half*)(smem + V_AF);

    uint4 pfA[2];
    auto ldA = [&](int c) {
#pragma unroll
        for (int i = 0; i < 2; i++) {
            int g = tid + i * 256;
            int m = g >> 3, kg = g & 7;
            pfA[i] = cvt8(A + (size_t)(row0 + m) * Dm + c * 64 + kg * 8);
        }
    };
    auto stsA = [&]() {
#pragma unroll
        for (int i = 0; i < 2; i++) {
            int g = tid + i * 256;
            int m = g >> 3, kg = g & 7;
            *(uint4*)&sAf[m * STR + kg * 8] = pfA[i];
        }
    };
    auto cpB = [&](int c, int buf) {
        uint32_t dst = sb + V_BF(buf);
#pragma unroll
        for (int i = 0; i < 8; i++) {
            int g = tid + i * 256;         // 2048 groups of 16B
            int n = g >> 3, kg = g & 7;
            cp_async16(dst + (uint32_t)(n * STR + kg * 8) * 2,
                       &g_Bf[n * Dm + c * 64 + kg * 8]);
        }
    };

    ldA(0);
    cpB(0, 0); CP_COMMIT();
    for (int c = 0; c < 4; c++) {
        stsA();                            // A buf free (trailing barrier c-1)
        if (c < 3) { cpB(c + 1, (c + 1) & 1); CP_COMMIT(); CP_WAIT1(); }
        else CP_WAIT0();
        __syncthreads();                   // chunk c's B visible to all
        if (c < 3) ldA(c + 1);
        mma_chunk1<4, 4>(sb + V_AF, sb + V_BF(c & 1), STR * 2, wm, wn, lane, acc);
        __syncthreads();                   // frees A buf + B buf (c-1 pattern)
    }

#pragma unroll
    for (int mt = 0; mt < 2; mt++)
#pragma unroll
        for (int nt = 0; nt < 8; nt++) {
            float* a4 = &acc[(mt * 8 + nt) * 4];
            int r = row0 + wm + mt * 16 + (lane >> 2);
            int cg = wn + nt * 8 + (lane & 3) * 2;
            float b0 = __ldg(&bias[cg]), b1 = __ldg(&bias[cg + 1]);
            *(__half2*)&g_value_h[(size_t)r * Dm + cg] =
                __floats2half2_rn(a4[0] + b0, a4[1] + b1);
            *(__half2*)&g_value_h[(size_t)(r + 8) * Dm + cg] =
                __floats2half2_rn(a4[2] + b0, a4[3] + b1);
        }
}

// =====================================================================
// K2: proj GEMM, BM=64 x BN=128, cp.async B. grid (4,50)
// =====================================================================
__global__ __launch_bounds__(256) void k_proj_mma(
    const float* __restrict__ boff, const float* __restrict__ baw,
    const float* __restrict__ bhs,  const float* __restrict__ bctx)
{
    extern __shared__ char smem[];
    uint32_t sb = smem_u32(smem);
    int tid = threadIdx.x;
    int w = tid >> 5, lane = tid & 31;
    int wm = (w >> 2) * 32, wn = (w & 3) * 32;
    int row0 = blockIdx.y * 64;
    int col0 = blockIdx.x * 128;

    float acc[32];
#pragma unroll
    for (int i = 0; i < 32; i++) acc[i] = 0.f;

    __half* sAf = (__half*)(smem + OFF_AF);

    uint4 pfA[2];
    auto ldA = [&](int c) {
        int xcol = (c < 4) ? (512 + c * 64) : (256 + (c - 4) * 64);
#pragma unroll
        for (int i = 0; i < 2; i++) {
            int g = tid + i * 256;
            int m = g >> 3, kg = g & 7;
            pfA[i] = *(const uint4*)&g_Xf[(size_t)(row0 + m) * 768 + xcol + kg * 8];
        }
    };
    auto stsA = [&]() {
#pragma unroll
        for (int i = 0; i < 2; i++) {
            int g = tid + i * 256;
            int m = g >> 3, kg = g & 7;
            *(uint4*)&sAf[m * STR + kg * 8] = pfA[i];
        }
    };
    auto cpB = [&](int c, int buf) {
        uint32_t dst = sb + OFF_BF(buf);
#pragma unroll
        for (int i = 0; i < 4; i++) {
            int g = tid + i * 256;         // 1024 groups
            int n = g >> 3, kg = g & 7;
            cp_async16(dst + (uint32_t)(n * STR + kg * 8) * 2,
                       &g_Pf[(col0 + n) * 512 + c * 64 + kg * 8]);
        }
    };

    ldA(0);
    cpB(0, 0); CP_COMMIT();
    for (int c = 0; c < 8; c++) {
        stsA();
        if (c < 7) { cpB(c + 1, (c + 1) & 1); CP_COMMIT(); CP_WAIT1(); }
        else CP_WAIT0();
        __syncthreads();
        if (c < 7) ldA(c + 1);
        mma_chunk1<2, 4>(sb + OFF_AF, sb + OFF_BF(c & 1), STR * 2, wm, wn, lane, acc);
        __syncthreads();
    }

    int bx = blockIdx.x;
#pragma unroll
    for (int mt = 0; mt < 2; mt++)
#pragma unroll
        for (int nt = 0; nt < 4; nt++) {
            float* a4 = &acc[(mt * 4 + nt) * 4];
            int r = row0 + wm + mt * 16 + (lane >> 2);
            int cl = wn + nt * 8 + (lane & 3) * 2;
            if (bx == 0) {
                float b0 = __ldg(&boff[cl]), b1 = __ldg(&boff[cl + 1]);
                *(float2*)&g_off[r * 128 + cl] = make_float2(a4[0] + b0, a4[1] + b1);
                *(float2*)&g_off[(r + 8) * 128 + cl] = make_float2(a4[2] + b0, a4[3] + b1);
            } else if (bx == 1) {
                float b0 = __ldg(&baw[cl]), b1 = __ldg(&baw[cl + 1]);
                *(float2*)&g_awl[r * 128 + cl] = make_float2(a4[0] + b0, a4[1] + b1);
                *(float2*)&g_awl[(r + 8) * 128 + cl] = make_float2(a4[2] + b0, a4[3] + b1);
            } else {
                int col = (bx - 2) * 128 + cl;
                float b0 = __ldg(&bhs[col]) + __ldg(&bctx[col]);
                float b1 = __ldg(&bhs[col + 1]) + __ldg(&bctx[col + 1]);
                *(float2*)&g_hsproj[r * 256 + col] = make_float2(a4[0] + b0, a4[1] + b1);
                *(float2*)&g_hsproj[(r + 8) * 256 + col] = make_float2(a4[2] + b0, a4[3] + b1);
            }
        }
}

// =====================================================================
// K3: sample + additive attention (fp16 value in, fp16 attnres out)
// =====================================================================
#define A3STR 40
#define S3_AF  0
#define S3_BF  10240
#define S3_ADD 30720
#define S3_WA  31744
#define S3_AW  32768
#define S3_SC  33280
#define S3_SMEM 33792

__global__ __launch_bounds__(256) void k_sample_attn(
    const float* __restrict__ rp,
    const float* __restrict__ Walpha)
{
    extern __shared__ char sm3[];
    __half* sAf3 = (__half*)(sm3 + S3_AF);
    __half* sBf3 = (__half*)(sm3 + S3_BF);
    float* add_s = (float*)(sm3 + S3_ADD);
    float* Wa_s  = (float*)(sm3 + S3_WA);
    float* aw_s  = (float*)(sm3 + S3_AW);
    float* sc_s  = (float*)(sm3 + S3_SC);

    int n = blockIdx.x;
    int tid = threadIdx.x;
    int w = tid >> 5, lane = tid & 31;
    int b = n / NQ;

    for (int g = tid; g < 1024; g += 256) {
        int r = g >> 2, kg = (g & 3) * 8;
        *(uint4*)&sBf3[r * A3STR + kg] = *(const uint4*)&g_Cf[r * 32 + kg];
    }
    if (tid < 128) { aw_s[tid] = g_awl[n * 128 + tid]; sc_s[tid] = 0.f; }
    add_s[tid] = g_hsproj[n * 256 + tid];
    Wa_s[tid] = Walpha[tid];
    __syncthreads();

    if (lane < 16) {
        float v = aw_s[w * 16 + lane];
        float mx = v;
#pragma unroll
        for (int o = 8; o > 0; o >>= 1)
            mx = fmaxf(mx, __shfl_xor_sync(0x0000ffffu, mx, o, 16));
        float ev = __expf(v - mx);
        float s = ev;
#pragma unroll
        for (int o = 8; o > 0; o >>= 1)
            s += __shfl_xor_sync(0x0000ffffu, s, o, 16);
        aw_s[w * 16 + lane] = ev / s;
    }
    __syncthreads();

    {
        const int TLS[4]    = {2048, 1024, 512, 256};
        const int STARTS[4] = {0, 2048, 3072, 3584};
        int pair = tid >> 1, half = tid & 1;
        int h2 = pair >> 4, lp = pair & 15, l = lp >> 2;
        int Tl = TLS[l], st = STARTS[l];
        float ref = rp[n * Ll + l];
        float off = g_off[n * HLP + pair];
        float aw = aw_s[pair];
        float x = ref * (float)Tl + off - 0.5f;
        float xf = floorf(x);
        float w1 = x - xf, w0 = 1.0f - w1;
        int i0 = (int)xf, i1 = i0 + 1;
        float wa0 = aw * w0 * ((i0 >= 0 && i0 < Tl) ? 1.f : 0.f);
        float wa1 = aw * w1 * ((i1 >= 0 && i1 < Tl) ? 1.f : 0.f);
        int c0i = min(max(i0, 0), Tl - 1);
        int c1i = min(max(i1, 0), Tl - 1);
        size_t base0 = ((size_t)(b * T_TOTAL + st + c0i)) * Dm + h2 * HD + half * 16;
        size_t base1 = ((size_t)(b * T_TOTAL + st + c1i)) * Dm + h2 * HD + half * 16;
        uint4 ua[2], ub[2];
        ua[0] = *(const uint4*)&g_value_h[base0];
        ua[1] = *(const uint4*)&g_value_h[base0 + 8];
        ub[0] = *(const uint4*)&g_value_h[base1];
        ub[1] = *(const uint4*)&g_value_h[base1 + 8];
        const __half2* ha = (const __half2*)ua;
        const __half2* hb = (const __half2*)ub;
        uint4 outv[2];
        __half2* ho = (__half2*)outv;
#pragma unroll
        for (int q2 = 0; q2 < 8; q2++) {
            float2 fa = __half22float2(ha[q2]);
            float2 fb = __half22float2(hb[q2]);
            ho[q2] = __floats2half2_rn(wa0 * fa.x + wa1 * fb.x,
                                       wa0 * fa.y + wa1 * fb.y);
        }
        int d = half * 16;
        *(uint4*)&sAf3[pair * A3STR + d]     = outv[0];
        *(uint4*)&sAf3[pair * A3STR + d + 8] = outv[1];
    }
    __syncthreads();

    uint32_t aF = smem_u32(sAf3);
    uint32_t bF = smem_u32(sBf3);
    int wm = (w >> 1) * 32, wnl = (w & 1) * 32;
    float scoreacc[2][2] = {{0.f, 0.f}, {0.f, 0.f}};

#pragma unroll
    for (int pass = 0; pass < 4; pass++) {
        uint32_t boff2 = (uint32_t)(pass * 64 * A3STR * 2);
        float acc[32];
#pragma unroll
        for (int i = 0; i < 32; i++) acc[i] = 0.f;
        mma_chunk1<2, 2>(aF, bF + boff2, A3STR * 2, wm, wnl, lane, acc);
#pragma unroll
        for (int mt = 0; mt < 2; mt++)
#pragma unroll
            for (int nt = 0; nt < 4; nt++) {
                float* a4 = &acc[(mt * 4 + nt) * 4];
                int e0 = pass * 64 + wnl + nt * 8 + (lane & 3) * 2;
                scoreacc[mt][0] += tanha(a4[0] + add_s[e0]) * Wa_s[e0];
                scoreacc[mt][0] += tanha(a4[1] + add_s[e0 + 1]) * Wa_s[e0 + 1];
                scoreacc[mt][1] += tanha(a4[2] + add_s[e0]) * Wa_s[e0];
                scoreacc[mt][1] += tanha(a4[3] + add_s[e0 + 1]) * Wa_s[e0 + 1];
            }
    }

#pragma unroll
    for (int mt = 0; mt < 2; mt++) {
        float s0 = scoreacc[mt][0], s1 = scoreacc[mt][1];
        s0 += __shfl_xor_sync(0xffffffffu, s0, 1);
        s0 += __shfl_xor_sync(0xffffffffu, s0, 2);
        s1 += __shfl_xor_sync(0xffffffffu, s1, 1);
        s1 += __shfl_xor_sync(0xffffffffu, s1, 2);
        if ((lane & 3) == 0) {
            atomicAdd(&sc_s[wm + mt * 16 + (lane >> 2)], s0);
            atomicAdd(&sc_s[wm + mt * 16 + 8 + (lane >> 2)], s1);
        }
    }
    __syncthreads();

    if (lane < 16) {
        float v = sc_s[w * 16 + lane];
        float mx = v;
#pragma unroll
        for (int o = 8; o > 0; o >>= 1)
            mx = fmaxf(mx, __shfl_xor_sync(0x0000ffffu, mx, o, 16));
        float ev = __expf(v - mx);
        float s = ev;
#pragma unroll
        for (int o = 8; o > 0; o >>= 1)
            s += __shfl_xor_sync(0x0000ffffu, s, o, 16);
        sc_s[w * 16 + lane] = ev / s;
    }
    __syncwarp();

    {
        float accw = 0.f;
#pragma unroll
        for (int p = 0; p < 16; p++) {
            int r = (w * 16 + p) * A3STR + lane;
            accw += sc_s[w * 16 + p] * __half2float(sAf3[r]);
        }
        g_ARf[(size_t)n * Dm + w * HD + lane] = __float2half_rn(accw);
    }
}

// =====================================================================
// K4a/K4b: gates GEMMs, cp.async B double-buffered
// =====================================================================
template<int NCHUNK, bool ACCUM>
__device__ __forceinline__ void gates_core(int tid)
{
    extern __shared__ char smem[];
    uint32_t sb = smem_u32(smem);
    int w = tid >> 5, lane = tid & 31;
    int wm = (w >> 2) * 32, wn = (w & 3) * 32;
    int row0 = blockIdx.y * 64;
    int col0 = blockIdx.x * 128;

    float acc[32];
#pragma unroll
    for (int i = 0; i < 32; i++) acc[i] = 0.f;

    __half* sAf = (__half*)(smem + OFF_AF);

    uint4 pfA[2];
    auto ldA = [&](int c) {
#pragma unroll
        for (int i = 0; i < 2; i++) {
            int g = tid + i * 256;
            int m = g >> 3, kg = g & 7;
            if (ACCUM)
                pfA[i] = *(const uint4*)&g_ARf[(size_t)(row0 + m) * 256 + c * 64 + kg * 8];
            else
                pfA[i] = *(const uint4*)&g_Xf[(size_t)(row0 + m) * 768 + c * 64 + kg * 8];
        }
    };
    auto stsA = [&]() {
#pragma unroll
        for (int i = 0; i < 2; i++) {
            int g = tid + i * 256;
            int m = g >> 3, kg = g & 7;
            *(uint4*)&sAf[m * STR + kg * 8] = pfA[i];
        }
    };
    auto kcol_of = [&](int c) {
        if (ACCUM) return 256 + c * 64;
        int seg = c >> 2;
        return ((seg == 0) ? 0 : (seg == 1) ? 512 : 768) + (c & 3) * 64;
    };
    auto cpB = [&](int c, int buf) {
        int kcol = kcol_of(c);
        uint32_t dst = sb + OFF_BF(buf);
#pragma unroll
        for (int i = 0; i < 4; i++) {
            int g = tid + i * 256;
            int n = g >> 3, kg = g & 7;
            cp_async16(dst + (uint32_t)(n * STR + kg * 8) * 2,
                       &g_Gf[(size_t)(col0 + n) * 1024 + kcol + kg * 8]);
        }
    };

    ldA(0);
    cpB(0, 0); CP_COMMIT();
    for (int c = 0; c < NCHUNK; c++) {
        stsA();
        if (c < NCHUNK - 1) { cpB(c + 1, (c + 1) & 1); CP_COMMIT(); CP_WAIT1(); }
        else CP_WAIT0();
        __syncthreads();
        if (c < NCHUNK - 1) ldA(c + 1);
        mma_chunk1<2, 4>(sb + OFF_AF, sb + OFF_BF(c & 1), STR * 2, wm, wn, lane, acc);
        __syncthreads();
    }

#pragma unroll
    for (int mt = 0; mt < 2; mt++)
#pragma unroll
        for (int nt = 0; nt < 4; nt++) {
            float* a4 = &acc[(mt * 4 + nt) * 4];
            int r = row0 + wm + mt * 16 + (lane >> 2);
            int cg = col0 + wn + nt * 8 + (lane & 3) * 2;
            float* p0 = &g_gates[(size_t)r * 1024 + cg];
            float* p1 = &g_gates[(size_t)(r + 8) * 1024 + cg];
            if (ACCUM) {
                float2 o0 = *(float2*)p0, o1 = *(float2*)p1;
                *(float2*)p0 = make_float2(o0.x + a4[0], o0.y + a4[1]);
                *(float2*)p1 = make_float2(o1.x + a4[2], o1.y + a4[3]);
            } else {
                *(float2*)p0 = make_float2(a4[0], a4[1]);
                *(float2*)p1 = make_float2(a4[2], a4[3]);
            }
        }
}

__global__ __launch_bounds__(256) void k_gates768()
{
    gates_core<12, false>(threadIdx.x);
}
__global__ __launch_bounds__(256) void k_gates256()
{
    gates_core<4, true>(threadIdx.x);
}

// =====================================================================
// K5: LSTM elementwise + output writes
// =====================================================================
__global__ __launch_bounds__(256) void k_lstm_ew(
    const float* __restrict__ c0, float* __restrict__ out, int write3)
{
    int n = blockIdx.x;
    int d = threadIdx.x;
    size_t g = (size_t)n * 1024;
    float gi = g_gates[g + d];
    float gf = g_gates[g + 256 + d];
    float gg = g_gates[g + 512 + d];
    float go = g_gates[g + 768 + d];
    float cprev = c0[(size_t)n * Dm + d];
    float cnew = sigm(gf) * cprev + sigm(gi) * tanh_fast(gg);
    float hnew = sigm(go) * tanh_fast(cnew);
    size_t idx = (size_t)n * Dm + d;
    out[idx] = hnew;
    if (write3) {
        out[(size_t)Nn * Dm + idx]     = hnew;
        out[(size_t)2 * Nn * Dm + idx] = cnew;
    }
}

// ---------------- streams/events (static init, outside capture) ----------
static cudaStream_t g_s1 = nullptr;
static cudaEvent_t g_e0 = nullptr, g_e_proj = nullptr, g_e_g768 = nullptr;
static bool g_streams_ok = false;
static struct StreamInit {
    StreamInit() {
        bool ok = true;
        ok &= (cudaStreamCreateWithFlags(&g_s1, cudaStreamNonBlocking) == cudaSuccess);
        ok &= (cudaEventCreateWithFlags(&g_e0, cudaEventDisableTiming) == cudaSuccess);
        ok &= (cudaEventCreateWithFlags(&g_e_proj, cudaEventDisableTiming) == cudaSuccess);
        ok &= (cudaEventCreateWithFlags(&g_e_g768, cudaEventDisableTiming) == cudaSuccess);
        g_streams_ok = ok;
    }
} g_stream_init;

// =====================================================================
// launch
// =====================================================================
extern "C" void kernel_launch(void* const* d_in, const int* in_sizes, int n_in,
                              void* d_out, int out_size)
{
    const float* token  = (const float*)d_in[0];
    const float* h0     = (const float*)d_in[1];
    const float* c0     = (const float*)d_in[2];
    const float* query  = (const float*)d_in[3];
    const float* rp     = (const float*)d_in[4];
    const float* ehs    = (const float*)d_in[5];
    const float* Wvalue = (const float*)d_in[8];
    const float* bvalue = (const float*)d_in[9];
    const float* Woff   = (const float*)d_in[10];
    const float* boff   = (const float*)d_in[11];
    const float* Waw    = (const float*)d_in[12];
    const float* baw    = (const float*)d_in[13];
    const float* Wctx   = (const float*)d_in[14];
    const float* bctx   = (const float*)d_in[15];
    const float* Whs    = (const float*)d_in[16];
    const float* bhs    = (const float*)d_in[17];
    const float* Walpha = (const float*)d_in[18];
    const float* Wih    = (const float*)d_in[20];
    const float* Whh    = (const float*)d_in[21];
    float* out = (float*)d_out;

    cudaFuncSetAttribute(k_value_mma,
                         cudaFuncAttributeMaxDynamicSharedMemorySize, V_SMEM);
    cudaFuncSetAttribute(k_proj_mma,
                         cudaFuncAttributeMaxDynamicSharedMemorySize, GEMM_SMEM);
    cudaFuncSetAttribute(k_sample_attn,
                         cudaFuncAttributeMaxDynamicSharedMemorySize, S3_SMEM);
    cudaFuncSetAttribute(k_gates768,
                         cudaFuncAttributeMaxDynamicSharedMemorySize, GEMM_SMEM);
    cudaFuncSetAttribute(k_gates256,
                         cudaFuncAttributeMaxDynamicSharedMemorySize, GEMM_SMEM);

    int write3 = (out_size >= 3 * Nn * Dm) ? 1 : 0;
    const int PREP_REST_BLOCKS = (1048576 + 8192 + 262144 + 255) / 256;  // 5152
    const int PREP_X_BLOCKS = (Nn * 768 + 255) / 256;                    // 9600

    if (g_streams_ok) {
        k_prep_B<<<256, 256>>>(Wvalue);
        cudaEventRecord(g_e0, 0);
        k_prep_x<<<PREP_X_BLOCKS, 256, 0, g_s1>>>(token, query, h0);
        cudaStreamWaitEvent(g_s1, g_e0, 0);
        k_prep_rest<<<PREP_REST_BLOCKS, 256, 0, g_s1>>>(Wih, Whh, Wctx, Woff, Waw, Whs);
        k_proj_mma<<<dim3(4, 50), 256, GEMM_SMEM, g_s1>>>(boff, baw, bhs, bctx);
        cudaEventRecord(g_e_proj, g_s1);
        k_gates768<<<dim3(8, 50), 256, GEMM_SMEM, g_s1>>>();
        cudaEventRecord(g_e_g768, g_s1);
        k_value_mma<<<1920, 256, V_SMEM>>>(ehs, bvalue);
        cudaStreamWaitEvent(0, g_e_proj, 0);
        k_sample_attn<<<Nn, 256, S3_SMEM>>>(rp, Walpha);
        cudaStreamWaitEvent(0, g_e_g768, 0);
        k_gates256<<<dim3(8, 50), 256, GEMM_SMEM>>>();
        k_lstm_ew<<<Nn, 256>>>(c0, out, write3);
    } else {
        k_prep_B<<<256, 256>>>(Wvalue);
        k_prep_x<<<PREP_X_BLOCKS, 256>>>(token, query, h0);
        k_prep_rest<<<PREP_REST_BLOCKS, 256>>>(Wih, Whh, Wctx, Woff, Waw, Whs);
        k_proj_mma<<<dim3(4, 50), 256, GEMM_SMEM>>>(boff, baw, bhs, bctx);
        k_gates768<<<dim3(8, 50), 256, GEMM_SMEM>>>();
        k_value_mma<<<1920, 256, V_SMEM>>>(ehs, bvalue);
        k_sample_attn<<<Nn, 256, S3_SMEM>>>(rp, Walpha);
        k_gates256<<<dim3(8, 50), 256, GEMM_SMEM>>>();
        k_lstm_ew<<<Nn, 256>>>(c0, out, write3);
    }
}

// round 16
// speedup vs baseline: 1.5154x; 1.0112x over previous
#include <cuda_runtime.h>
#include <cuda_fp16.h>
#include <cstdint>

// ---------------- problem constants ----------------
#define Dm 256
#define Hh 8
#define HD 32
#define Ll 4
#define Pp 4
#define Bb 32
#define NQ 100
#define Nn (Bb*NQ)          // 3200
#define T_TOTAL 3840
#define LP 16
#define HLP 128

// ---------------- device scratch ----------------
__device__ __half g_value_h[(size_t)Bb * T_TOTAL * Dm];   // ~63MB (fp16)
__device__ float g_off[Nn * HLP];
__device__ float g_awl[Nn * HLP];
__device__ float g_hsproj[Nn * Dm];
__device__ __half g_ARf[Nn * Dm];          // attnres fp16
__device__ float g_gates[Nn * 4 * Dm];
__device__ __half g_Xf[(size_t)Nn * 768];  // [token|query|h0] fp16
// weights: single fp16
__device__ __half g_Bf[Dm * Dm];        // W_value^T [n][k]
__device__ __half g_Gf[1024 * 1024];    // [Wih|Whh] [j][k]
__device__ __half g_Cf[256 * 32];       // Wctx^T [e][d]
__device__ __half g_Pf[512 * 512];      // proj B [n][k]

__device__ __forceinline__ float tanh_fast(float x) {
    float e = __expf(2.0f * x);
    return 1.0f - 2.0f / (e + 1.0f);
}
__device__ __forceinline__ float tanha(float x) {
    float y;
    asm("tanh.approx.f32 %0, %1;" : "=f"(y) : "f"(x));
    return y;
}
__device__ __forceinline__ float sigm(float x) {
    return 1.0f / (1.0f + __expf(-x));
}
__device__ __forceinline__ uint32_t smem_u32(const void* p) {
    uint32_t a;
    asm("{ .reg .u64 t; cvta.to.shared.u64 t, %1; cvt.u32.u64 %0, t; }"
        : "=r"(a) : "l"(p));
    return a;
}

// ---------------- cp.async ----------------
__device__ __forceinline__ void cp_async16(uint32_t dst, const void* src) {
    asm volatile("cp.async.cg.shared.global [%0], [%1], 16;"
                 :: "r"(dst), "l"(src) : "memory");
}
#define CP_COMMIT() asm volatile("cp.async.commit_group;" ::: "memory")
#define CP_WAIT1()  asm volatile("cp.async.wait_group 1;" ::: "memory")
#define CP_WAIT0()  asm volatile("cp.async.wait_group 0;" ::: "memory")

// ---------------- mma.sync / ldmatrix (fp16) ----------------
__device__ __forceinline__ void ldm_x4(uint32_t* r, uint32_t addr) {
    asm volatile("ldmatrix.sync.aligned.m8n8.x4.shared.b16 {%0,%1,%2,%3}, [%4];"
        : "=r"(r[0]), "=r"(r[1]), "=r"(r[2]), "=r"(r[3]) : "r"(addr));
}
#define MMAH(d, a, b) \
    asm volatile("mma.sync.aligned.m16n8k16.row.col.f32.f16.f16.f32 " \
        "{%0,%1,%2,%3}, {%4,%5,%6,%7}, {%8,%9}, {%0,%1,%2,%3};" \
        : "+f"((d)[0]), "+f"((d)[1]), "+f"((d)[2]), "+f"((d)[3]) \
        : "r"((a)[0]), "r"((a)[1]), "r"((a)[2]), "r"((a)[3]), \
          "r"((b)[0]), "r"((b)[1]))

// single-term chunk: A x B, both fp16. warp tile 32m x (NT2*16)n
template<int NT2, int KS>
__device__ __forceinline__ void mma_chunk1(
    uint32_t aF, uint32_t bF,
    uint32_t stride2, int wm, int wn, int lane, float* acc)
{
    int arow = lane & 15, acol8 = (lane >> 4) * 8;
    int brow = ((lane >> 4) & 1) * 8 + (lane & 7);
    int bcol8 = ((lane >> 3) & 1) * 8;
#pragma unroll
    for (int ks = 0; ks < KS; ks++) {
        uint32_t Af[2][4], B[NT2][4];
#pragma unroll
        for (int mt = 0; mt < 2; mt++) {
            uint32_t off = (uint32_t)(wm + mt * 16 + arow) * stride2
                         + (uint32_t)(ks * 16 + acol8) * 2;
            ldm_x4(Af[mt], aF + off);
        }
#pragma unroll
        for (int nt2 = 0; nt2 < NT2; nt2++) {
            uint32_t off = (uint32_t)(wn + nt2 * 16 + brow) * stride2
                         + (uint32_t)(ks * 16 + bcol8) * 2;
            ldm_x4(B[nt2], bF + off);
        }
#pragma unroll
        for (int mt = 0; mt < 2; mt++)
#pragma unroll
            for (int nt = 0; nt < 2 * NT2; nt++)
                MMAH(acc + (mt * 2 * NT2 + nt) * 4, Af[mt],
                     (&B[nt >> 1][(nt & 1) * 2]));
    }
}

#define STR 72
// generic GEMM: A 9216, B double buf 2x18432
#define OFF_AF 0
#define OFF_BF(b) (9216 + (b) * 18432)
#define GEMM_SMEM 46080
// value: A 9216, B double buf 2x36864
#define V_AF 0
#define V_BF(b) (9216 + (b) * 36864)
#define V_SMEM 82944

__device__ __forceinline__ uint4 cvt8(const float* s) {
    float4 v0 = *(const float4*)s;
    float4 v1 = *(const float4*)(s + 4);
    __half hh[8];
    hh[0] = __float2half_rn(v0.x); hh[1] = __float2half_rn(v0.y);
    hh[2] = __float2half_rn(v0.z); hh[3] = __float2half_rn(v0.w);
    hh[4] = __float2half_rn(v1.x); hh[5] = __float2half_rn(v1.y);
    hh[6] = __float2half_rn(v1.z); hh[7] = __float2half_rn(v1.w);
    return *(uint4*)hh;
}

// =====================================================================
// K0a: prep W_value -> fp16 (transposed)
// =====================================================================
__global__ __launch_bounds__(256) void k_prep_B(const float* __restrict__ Wvalue)
{
    int idx = blockIdx.x * 256 + threadIdx.x;   // < 65536
    int n = idx >> 8, k = idx & 255;
    g_Bf[idx] = __float2half_rn(Wvalue[k * Dm + n]);
}

// =====================================================================
// K0c: prep activations -> fp16 [token|query|h0] per row
// =====================================================================
__global__ __launch_bounds__(256) void k_prep_x(
    const float* __restrict__ token, const float* __restrict__ query,
    const float* __restrict__ h0)
{
    int idx = blockIdx.x * 256 + threadIdx.x;
    int n = idx / 768, col = idx - n * 768;
    float v;
    if (col < 256)      v = token[n * 256 + col];
    else if (col < 512) v = query[n * 256 + (col - 256)];
    else                v = h0[n * 256 + (col - 512)];
    g_Xf[idx] = __float2half_rn(v);
}

// =====================================================================
// K0b: prep remaining weights -> fp16
// =====================================================================
__global__ __launch_bounds__(256) void k_prep_rest(
    const float* __restrict__ Wih, const float* __restrict__ Whh,
    const float* __restrict__ Wctx,
    const float* __restrict__ Woff, const float* __restrict__ Waw,
    const float* __restrict__ Whs)
{
    int idx = blockIdx.x * 256 + threadIdx.x;
    if (idx < 1048576) {
        int j = idx >> 10, k = idx & 1023;
        float v = (k < 768) ? Wih[(size_t)j * 768 + k]
                            : Whh[(size_t)j * 256 + (k - 768)];
        g_Gf[idx] = __float2half_rn(v);
    } else if (idx < 1048576 + 8192) {
        int i = idx - 1048576;
        int e = i >> 5, k = i & 31;
        g_Cf[i] = __float2half_rn(Wctx[k * 256 + e]);
    } else if (idx < 1056768 + 262144) {
        int i = idx - 1056768;
        int n = i >> 9, k = i & 511;
        float v;
        if (n < 128)      v = Woff[k * 128 + n];
        else if (n < 256) v = Waw[k * 128 + (n - 128)];
        else              v = (k < 256) ? Whs[k * 256 + (n - 256)] : 0.f;
        g_Pf[i] = __float2half_rn(v);
    }
}

// =====================================================================
// K1: value GEMM (fp16, cp.async double-buffered B). grid 1920, BM=64
// =====================================================================
__global__ __launch_bounds__(256, 2) void k_value_mma(
    const float* __restrict__ A, const float* __restrict__ bias)
{
    extern __shared__ char smem[];
    uint32_t sb = smem_u32(smem);
    int tid = threadIdx.x;
    int w = tid >> 5, lane = tid & 31;
    int wm = (w >> 2) * 32, wn = (w & 3) * 64;
    int row0 = blockIdx.x * 64;

    float acc[64];
#pragma unroll
    for (int i = 0; i < 64; i++) acc[i] = 0.f;

    __half* sAf = (__half*)(smem + V_AF);

    uint4 pfA[2];
    auto ldA = [&](int c) {
#pragma unroll
        for (int i = 0; i < 2; i++) {
            int g = tid + i * 256;
            int m = g >> 3, kg = g & 7;
            pfA[i] = cvt8(A + (size_t)(row0 + m) * Dm + c * 64 + kg * 8);
        }
    };
    auto stsA = [&]() {
#pragma unroll
        for (int i = 0; i < 2; i++) {
            int g = tid + i * 256;
            int m = g >> 3, kg = g & 7;
            *(uint4*)&sAf[m * STR + kg * 8] = pfA[i];
        }
    };
    auto cpB = [&](int c, int buf) {
        uint32_t dst = sb + V_BF(buf);
#pragma unroll
        for (int i = 0; i < 8; i++) {
            int g = tid + i * 256;
            int n = g >> 3, kg = g & 7;
            cp_async16(dst + (uint32_t)(n * STR + kg * 8) * 2,
                       &g_Bf[n * Dm + c * 64 + kg * 8]);
        }
    };

    ldA(0);
    cpB(0, 0); CP_COMMIT();
    for (int c = 0; c < 4; c++) {
        stsA();
        if (c < 3) { cpB(c + 1, (c + 1) & 1); CP_COMMIT(); CP_WAIT1(); }
        else CP_WAIT0();
        __syncthreads();
        if (c < 3) ldA(c + 1);
        mma_chunk1<4, 4>(sb + V_AF, sb + V_BF(c & 1), STR * 2, wm, wn, lane, acc);
        __syncthreads();
    }

#pragma unroll
    for (int mt = 0; mt < 2; mt++)
#pragma unroll
        for (int nt = 0; nt < 8; nt++) {
            float* a4 = &acc[(mt * 8 + nt) * 4];
            int r = row0 + wm + mt * 16 + (lane >> 2);
            int cg = wn + nt * 8 + (lane & 3) * 2;
            float b0 = __ldg(&bias[cg]), b1 = __ldg(&bias[cg + 1]);
            *(__half2*)&g_value_h[(size_t)r * Dm + cg] =
                __floats2half2_rn(a4[0] + b0, a4[1] + b1);
            *(__half2*)&g_value_h[(size_t)(r + 8) * Dm + cg] =
                __floats2half2_rn(a4[2] + b0, a4[3] + b1);
        }
}

// =====================================================================
// K2: proj GEMM, BM=64 x BN=128, cp.async B. grid (4,50)
// =====================================================================
__global__ __launch_bounds__(256) void k_proj_mma(
    const float* __restrict__ boff, const float* __restrict__ baw,
    const float* __restrict__ bhs,  const float* __restrict__ bctx)
{
    extern __shared__ char smem[];
    uint32_t sb = smem_u32(smem);
    int tid = threadIdx.x;
    int w = tid >> 5, lane = tid & 31;
    int wm = (w >> 2) * 32, wn = (w & 3) * 32;
    int row0 = blockIdx.y * 64;
    int col0 = blockIdx.x * 128;

    float acc[32];
#pragma unroll
    for (int i = 0; i < 32; i++) acc[i] = 0.f;

    __half* sAf = (__half*)(smem + OFF_AF);

    uint4 pfA[2];
    auto ldA = [&](int c) {
        int xcol = (c < 4) ? (512 + c * 64) : (256 + (c - 4) * 64);
#pragma unroll
        for (int i = 0; i < 2; i++) {
            int g = tid + i * 256;
            int m = g >> 3, kg = g & 7;
            pfA[i] = *(const uint4*)&g_Xf[(size_t)(row0 + m) * 768 + xcol + kg * 8];
        }
    };
    auto stsA = [&]() {
#pragma unroll
        for (int i = 0; i < 2; i++) {
            int g = tid + i * 256;
            int m = g >> 3, kg = g & 7;
            *(uint4*)&sAf[m * STR + kg * 8] = pfA[i];
        }
    };
    auto cpB = [&](int c, int buf) {
        uint32_t dst = sb + OFF_BF(buf);
#pragma unroll
        for (int i = 0; i < 4; i++) {
            int g = tid + i * 256;
            int n = g >> 3, kg = g & 7;
            cp_async16(dst + (uint32_t)(n * STR + kg * 8) * 2,
                       &g_Pf[(col0 + n) * 512 + c * 64 + kg * 8]);
        }
    };

    ldA(0);
    cpB(0, 0); CP_COMMIT();
    for (int c = 0; c < 8; c++) {
        stsA();
        if (c < 7) { cpB(c + 1, (c + 1) & 1); CP_COMMIT(); CP_WAIT1(); }
        else CP_WAIT0();
        __syncthreads();
        if (c < 7) ldA(c + 1);
        mma_chunk1<2, 4>(sb + OFF_AF, sb + OFF_BF(c & 1), STR * 2, wm, wn, lane, acc);
        __syncthreads();
    }

    int bx = blockIdx.x;
#pragma unroll
    for (int mt = 0; mt < 2; mt++)
#pragma unroll
        for (int nt = 0; nt < 4; nt++) {
            float* a4 = &acc[(mt * 4 + nt) * 4];
            int r = row0 + wm + mt * 16 + (lane >> 2);
            int cl = wn + nt * 8 + (lane & 3) * 2;
            if (bx == 0) {
                float b0 = __ldg(&boff[cl]), b1 = __ldg(&boff[cl + 1]);
                *(float2*)&g_off[r * 128 + cl] = make_float2(a4[0] + b0, a4[1] + b1);
                *(float2*)&g_off[(r + 8) * 128 + cl] = make_float2(a4[2] + b0, a4[3] + b1);
            } else if (bx == 1) {
                float b0 = __ldg(&baw[cl]), b1 = __ldg(&baw[cl + 1]);
                *(float2*)&g_awl[r * 128 + cl] = make_float2(a4[0] + b0, a4[1] + b1);
                *(float2*)&g_awl[(r + 8) * 128 + cl] = make_float2(a4[2] + b0, a4[3] + b1);
            } else {
                int col = (bx - 2) * 128 + cl;
                float b0 = __ldg(&bhs[col]) + __ldg(&bctx[col]);
                float b1 = __ldg(&bhs[col + 1]) + __ldg(&bctx[col + 1]);
                *(float2*)&g_hsproj[r * 256 + col] = make_float2(a4[0] + b0, a4[1] + b1);
                *(float2*)&g_hsproj[(r + 8) * 256 + col] = make_float2(a4[2] + b0, a4[3] + b1);
            }
        }
}

// =====================================================================
// K3: sample + additive attention, 2 queries per CTA. grid 1600.
// warp w: query w>>2, rows (w&3)*32..+32 (= heads 2(w&3), 2(w&3)+1)
// smem: Wctx 20480 | A 2x10240 | add 2048 | Wa 1024 | aw 1024 | sc 1024
// =====================================================================
#define A3STR 40
#define S3_BF   0
#define S3_AF(q) (20480 + (q) * 10240)
#define S3_ADD  40960
#define S3_WA   43008
#define S3_AW   44032
#define S3_SC   45056
#define S3_SMEM 46080

__global__ __launch_bounds__(256) void k_sample_attn(
    const float* __restrict__ rp,
    const float* __restrict__ Walpha)
{
    extern __shared__ char sm3[];
    __half* sBf3 = (__half*)(sm3 + S3_BF);
    float* add_s = (float*)(sm3 + S3_ADD);   // [2][256]
    float* Wa_s  = (float*)(sm3 + S3_WA);    // [256]
    float* aw_s  = (float*)(sm3 + S3_AW);    // [2][128]
    float* sc_s  = (float*)(sm3 + S3_SC);    // [2][128]

    int n0 = blockIdx.x * 2;
    int tid = threadIdx.x;
    int w = tid >> 5, lane = tid & 31;

    // stage Wctx (shared by both queries)
    for (int g = tid; g < 1024; g += 256) {
        int r = g >> 2, kg = (g & 3) * 8;
        *(uint4*)&sBf3[r * A3STR + kg] = *(const uint4*)&g_Cf[r * 32 + kg];
    }
    // aw logits: 2x128
    {
        int q = tid >> 7, i = tid & 127;
        aw_s[q * 128 + i] = g_awl[(n0 + q) * 128 + i];
    }
    // adds: 2x256
    for (int g = tid; g < 512; g += 256) {
        int q = g >> 8, e = g & 255;
        add_s[g] = g_hsproj[(size_t)(n0 + q) * 256 + e];
    }
    Wa_s[tid] = Walpha[tid];
    __syncthreads();

    // aw softmax: warp w -> query w>>2, heads 2*(w&3) + (lane>>4); 16-lane groups
    {
        int q = w >> 2, h2 = 2 * (w & 3) + (lane >> 4);
        int li = lane & 15;
        float v = aw_s[q * 128 + h2 * 16 + li];
        float mx = v;
#pragma unroll
        for (int o = 8; o > 0; o >>= 1)
            mx = fmaxf(mx, __shfl_xor_sync(0xffffffffu, mx, o, 16));
        float ev = __expf(v - mx);
        float s = ev;
#pragma unroll
        for (int o = 8; o > 0; o >>= 1)
            s += __shfl_xor_sync(0xffffffffu, s, o, 16);
        aw_s[q * 128 + h2 * 16 + li] = ev / s;
    }
    __syncthreads();

    // gather: thread t -> query t>>7, pair t&127; 32 d values
    {
        const int TLS[4]    = {2048, 1024, 512, 256};
        const int STARTS[4] = {0, 2048, 3072, 3584};
        int q = tid >> 7, pair = tid & 127;
        int n = n0 + q;
        int b = n / NQ;
        int h2 = pair >> 4, lp = pair & 15, l = lp >> 2;
        int Tl = TLS[l], st = STARTS[l];
        float ref = rp[n * Ll + l];
        float off = g_off[n * HLP + pair];
        float aw = aw_s[q * 128 + pair];
        float x = ref * (float)Tl + off - 0.5f;
        float xf = floorf(x);
        float w1 = x - xf, w0 = 1.0f - w1;
        int i0 = (int)xf, i1 = i0 + 1;
        float wa0 = aw * w0 * ((i0 >= 0 && i0 < Tl) ? 1.f : 0.f);
        float wa1 = aw * w1 * ((i1 >= 0 && i1 < Tl) ? 1.f : 0.f);
        int c0i = min(max(i0, 0), Tl - 1);
        int c1i = min(max(i1, 0), Tl - 1);
        size_t base0 = ((size_t)(b * T_TOTAL + st + c0i)) * Dm + h2 * HD;
        size_t base1 = ((size_t)(b * T_TOTAL + st + c1i)) * Dm + h2 * HD;
        __half* dstA = (__half*)(sm3 + S3_AF(q)) + pair * A3STR;
#pragma unroll
        for (int hqd = 0; hqd < 4; hqd++) {        // 4 x 8 halves = 32 d
            uint4 ua = *(const uint4*)&g_value_h[base0 + hqd * 8];
            uint4 ub = *(const uint4*)&g_value_h[base1 + hqd * 8];
            const __half2* ha = (const __half2*)&ua;
            const __half2* hb = (const __half2*)&ub;
            uint4 outv;
            __half2* ho = (__half2*)&outv;
#pragma unroll
            for (int q2 = 0; q2 < 4; q2++) {
                float2 fa = __half22float2(ha[q2]);
                float2 fb = __half22float2(hb[q2]);
                ho[q2] = __floats2half2_rn(wa0 * fa.x + wa1 * fb.x,
                                           wa0 * fa.y + wa1 * fb.y);
            }
            *(uint4*)&dstA[hqd * 8] = outv;
        }
    }
    __syncthreads();

    // mma: warp w -> query q, rows w4*32..+32; loop 8 n-tiles of 32 e-cols
    int q = w >> 2, w4 = w & 3;
    uint32_t aF = smem_u32(sm3 + S3_AF(q));
    uint32_t bF = smem_u32(sBf3);
    int wm = w4 * 32;
    float scoreacc[2][2] = {{0.f, 0.f}, {0.f, 0.f}};

#pragma unroll
    for (int pass = 0; pass < 8; pass++) {
        float acc[32];
#pragma unroll
        for (int i = 0; i < 32; i++) acc[i] = 0.f;
        mma_chunk1<2, 2>(aF, bF, A3STR * 2, wm, pass * 32, lane, acc);
#pragma unroll
        for (int mt = 0; mt < 2; mt++)
#pragma unroll
            for (int nt = 0; nt < 4; nt++) {
                float* a4 = &acc[(mt * 4 + nt) * 4];
                int e0 = pass * 32 + nt * 8 + (lane & 3) * 2;
                scoreacc[mt][0] += tanha(a4[0] + add_s[q * 256 + e0]) * Wa_s[e0];
                scoreacc[mt][0] += tanha(a4[1] + add_s[q * 256 + e0 + 1]) * Wa_s[e0 + 1];
                scoreacc[mt][1] += tanha(a4[2] + add_s[q * 256 + e0]) * Wa_s[e0];
                scoreacc[mt][1] += tanha(a4[3] + add_s[q * 256 + e0 + 1]) * Wa_s[e0 + 1];
            }
    }

    // intra-warp quad reduce (e-dim), direct store (rows exclusive per warp)
#pragma unroll
    for (int mt = 0; mt < 2; mt++) {
        float s0 = scoreacc[mt][0], s1 = scoreacc[mt][1];
        s0 += __shfl_xor_sync(0xffffffffu, s0, 1);
        s0 += __shfl_xor_sync(0xffffffffu, s0, 2);
        s1 += __shfl_xor_sync(0xffffffffu, s1, 1);
        s1 += __shfl_xor_sync(0xffffffffu, s1, 2);
        if ((lane & 3) == 0) {
            sc_s[q * 128 + wm + mt * 16 + (lane >> 2)] = s0;
            sc_s[q * 128 + wm + mt * 16 + 8 + (lane >> 2)] = s1;
        }
    }
    __syncwarp();

    // softmax over 16 points: warp's 32 rows = heads 2*w4 + (lane>>4)
    {
        int h2 = 2 * w4 + (lane >> 4);
        int li = lane & 15;
        float v = sc_s[q * 128 + h2 * 16 + li];
        float mx = v;
#pragma unroll
        for (int o = 8; o > 0; o >>= 1)
            mx = fmaxf(mx, __shfl_xor_sync(0xffffffffu, mx, o, 16));
        float ev = __expf(v - mx);
        float s = ev;
#pragma unroll
        for (int o = 8; o > 0; o >>= 1)
            s += __shfl_xor_sync(0xffffffffu, s, o, 16);
        sc_s[q * 128 + h2 * 16 + li] = ev / s;
    }
    __syncwarp();

    // weighted sum: warp's 2 heads; lane = d
    {
        const __half* srcA = (const __half*)(sm3 + S3_AF(q));
#pragma unroll
        for (int hh = 0; hh < 2; hh++) {
            int h2 = 2 * w4 + hh;
            float accw = 0.f;
#pragma unroll
            for (int p = 0; p < 16; p++) {
                int r = (h2 * 16 + p) * A3STR + lane;
                accw += sc_s[q * 128 + h2 * 16 + p] * __half2float(srcA[r]);
            }
            g_ARf[(size_t)(n0 + q) * Dm + h2 * HD + lane] = __float2half_rn(accw);
        }
    }
}

// =====================================================================
// K4a/K4b: gates GEMMs, cp.async B double-buffered
// =====================================================================
template<int NCHUNK, bool ACCUM>
__device__ __forceinline__ void gates_core(int tid)
{
    extern __shared__ char smem[];
    uint32_t sb = smem_u32(smem);
    int w = tid >> 5, lane = tid & 31;
    int wm = (w >> 2) * 32, wn = (w & 3) * 32;
    int row0 = blockIdx.y * 64;
    int col0 = blockIdx.x * 128;

    float acc[32];
#pragma unroll
    for (int i = 0; i < 32; i++) acc[i] = 0.f;

    __half* sAf = (__half*)(smem + OFF_AF);

    uint4 pfA[2];
    auto ldA = [&](int c) {
#pragma unroll
        for (int i = 0; i < 2; i++) {
            int g = tid + i * 256;
            int m = g >> 3, kg = g & 7;
            if (ACCUM)
                pfA[i] = *(const uint4*)&g_ARf[(size_t)(row0 + m) * 256 + c * 64 + kg * 8];
            else
                pfA[i] = *(const uint4*)&g_Xf[(size_t)(row0 + m) * 768 + c * 64 + kg * 8];
        }
    };
    auto stsA = [&]() {
#pragma unroll
        for (int i = 0; i < 2; i++) {
            int g = tid + i * 256;
            int m = g >> 3, kg = g & 7;
            *(uint4*)&sAf[m * STR + kg * 8] = pfA[i];
        }
    };
    auto kcol_of = [&](int c) {
        if (ACCUM) return 256 + c * 64;
        int seg = c >> 2;
        return ((seg == 0) ? 0 : (seg == 1) ? 512 : 768) + (c & 3) * 64;
    };
    auto cpB = [&](int c, int buf) {
        int kcol = kcol_of(c);
        uint32_t dst = sb + OFF_BF(buf);
#pragma unroll
        for (int i = 0; i < 4; i++) {
            int g = tid + i * 256;
            int n = g >> 3, kg = g & 7;
            cp_async16(dst + (uint32_t)(n * STR + kg * 8) * 2,
                       &g_Gf[(size_t)(col0 + n) * 1024 + kcol + kg * 8]);
        }
    };

    ldA(0);
    cpB(0, 0); CP_COMMIT();
    for (int c = 0; c < NCHUNK; c++) {
        stsA();
        if (c < NCHUNK - 1) { cpB(c + 1, (c + 1) & 1); CP_COMMIT(); CP_WAIT1(); }
        else CP_WAIT0();
        __syncthreads();
        if (c < NCHUNK - 1) ldA(c + 1);
        mma_chunk1<2, 4>(sb + OFF_AF, sb + OFF_BF(c & 1), STR * 2, wm, wn, lane, acc);
        __syncthreads();
    }

#pragma unroll
    for (int mt = 0; mt < 2; mt++)
#pragma unroll
        for (int nt = 0; nt < 4; nt++) {
            float* a4 = &acc[(mt * 4 + nt) * 4];
            int r = row0 + wm + mt * 16 + (lane >> 2);
            int cg = col0 + wn + nt * 8 + (lane & 3) * 2;
            float* p0 = &g_gates[(size_t)r * 1024 + cg];
            float* p1 = &g_gates[(size_t)(r + 8) * 1024 + cg];
            if (ACCUM) {
                float2 o0 = *(float2*)p0, o1 = *(float2*)p1;
                *(float2*)p0 = make_float2(o0.x + a4[0], o0.y + a4[1]);
                *(float2*)p1 = make_float2(o1.x + a4[2], o1.y + a4[3]);
            } else {
                *(float2*)p0 = make_float2(a4[0], a4[1]);
                *(float2*)p1 = make_float2(a4[2], a4[3]);
            }
        }
}

__global__ __launch_bounds__(256) void k_gates768()
{
    gates_core<12, false>(threadIdx.x);
}
__global__ __launch_bounds__(256) void k_gates256()
{
    gates_core<4, true>(threadIdx.x);
}

// =====================================================================
// K5: LSTM elementwise + output writes
// =====================================================================
__global__ __launch_bounds__(256) void k_lstm_ew(
    const float* __restrict__ c0, float* __restrict__ out, int write3)
{
    int n = blockIdx.x;
    int d = threadIdx.x;
    size_t g = (size_t)n * 1024;
    float gi = g_gates[g + d];
    float gf = g_gates[g + 256 + d];
    float gg = g_gates[g + 512 + d];
    float go = g_gates[g + 768 + d];
    float cprev = c0[(size_t)n * Dm + d];
    float cnew = sigm(gf) * cprev + sigm(gi) * tanh_fast(gg);
    float hnew = sigm(go) * tanh_fast(cnew);
    size_t idx = (size_t)n * Dm + d;
    out[idx] = hnew;
    if (write3) {
        out[(size_t)Nn * Dm + idx]     = hnew;
        out[(size_t)2 * Nn * Dm + idx] = cnew;
    }
}

// ---------------- streams/events (static init, outside capture) ----------
static cudaStream_t g_s1 = nullptr;
static cudaEvent_t g_e0 = nullptr, g_e_proj = nullptr, g_e_g768 = nullptr;
static bool g_streams_ok = false;
static struct StreamInit {
    StreamInit() {
        bool ok = true;
        ok &= (cudaStreamCreateWithFlags(&g_s1, cudaStreamNonBlocking) == cudaSuccess);
        ok &= (cudaEventCreateWithFlags(&g_e0, cudaEventDisableTiming) == cudaSuccess);
        ok &= (cudaEventCreateWithFlags(&g_e_proj, cudaEventDisableTiming) == cudaSuccess);
        ok &= (cudaEventCreateWithFlags(&g_e_g768, cudaEventDisableTiming) == cudaSuccess);
        g_streams_ok = ok;
    }
} g_stream_init;

// =====================================================================
// launch
// =====================================================================
extern "C" void kernel_launch(void* const* d_in, const int* in_sizes, int n_in,
                              void* d_out, int out_size)
{
    const float* token  = (const float*)d_in[0];
    const float* h0     = (const float*)d_in[1];
    const float* c0     = (const float*)d_in[2];
    const float* query  = (const float*)d_in[3];
    const float* rp     = (const float*)d_in[4];
    const float* ehs    = (const float*)d_in[5];
    const float* Wvalue = (const float*)d_in[8];
    const float* bvalue = (const float*)d_in[9];
    const float* Woff   = (const float*)d_in[10];
    const float* boff   = (const float*)d_in[11];
    const float* Waw    = (const float*)d_in[12];
    const float* baw    = (const float*)d_in[13];
    const float* Wctx   = (const float*)d_in[14];
    const float* bctx   = (const float*)d_in[15];
    const float* Whs    = (const float*)d_in[16];
    const float* bhs    = (const float*)d_in[17];
    const float* Walpha = (const float*)d_in[18];
    const float* Wih    = (const float*)d_in[20];
    const float* Whh    = (const float*)d_in[21];
    float* out = (float*)d_out;

    cudaFuncSetAttribute(k_value_mma,
                         cudaFuncAttributeMaxDynamicSharedMemorySize, V_SMEM);
    cudaFuncSetAttribute(k_proj_mma,
                         cudaFuncAttributeMaxDynamicSharedMemorySize, GEMM_SMEM);
    cudaFuncSetAttribute(k_sample_attn,
                         cudaFuncAttributeMaxDynamicSharedMemorySize, S3_SMEM);
    cudaFuncSetAttribute(k_gates768,
                         cudaFuncAttributeMaxDynamicSharedMemorySize, GEMM_SMEM);
    cudaFuncSetAttribute(k_gates256,
                         cudaFuncAttributeMaxDynamicSharedMemorySize, GEMM_SMEM);

    int write3 = (out_size >= 3 * Nn * Dm) ? 1 : 0;
    const int PREP_REST_BLOCKS = (1048576 + 8192 + 262144 + 255) / 256;  // 5152
    const int PREP_X_BLOCKS = (Nn * 768 + 255) / 256;                    // 9600

    if (g_streams_ok) {
        k_prep_B<<<256, 256>>>(Wvalue);
        cudaEventRecord(g_e0, 0);
        k_prep_x<<<PREP_X_BLOCKS, 256, 0, g_s1>>>(token, query, h0);
        cudaStreamWaitEvent(g_s1, g_e0, 0);
        k_prep_rest<<<PREP_REST_BLOCKS, 256, 0, g_s1>>>(Wih, Whh, Wctx, Woff, Waw, Whs);
        k_proj_mma<<<dim3(4, 50), 256, GEMM_SMEM, g_s1>>>(boff, baw, bhs, bctx);
        cudaEventRecord(g_e_proj, g_s1);
        k_gates768<<<dim3(8, 50), 256, GEMM_SMEM, g_s1>>>();
        cudaEventRecord(g_e_g768, g_s1);
        k_value_mma<<<1920, 256, V_SMEM>>>(ehs, bvalue);
        cudaStreamWaitEvent(0, g_e_proj, 0);
        k_sample_attn<<<Nn / 2, 256, S3_SMEM>>>(rp, Walpha);
        cudaStreamWaitEvent(0, g_e_g768, 0);
        k_gates256<<<dim3(8, 50), 256, GEMM_SMEM>>>();
        k_lstm_ew<<<Nn, 256>>>(c0, out, write3);
    } else {
        k_prep_B<<<256, 256>>>(Wvalue);
        k_prep_x<<<PREP_X_BLOCKS, 256>>>(token, query, h0);
        k_prep_rest<<<PREP_REST_BLOCKS, 256>>>(Wih, Whh, Wctx, Woff, Waw, Whs);
        k_proj_mma<<<dim3(4, 50), 256, GEMM_SMEM>>>(boff, baw, bhs, bctx);
        k_gates768<<<dim3(8, 50), 256, GEMM_SMEM>>>();
        k_value_mma<<<1920, 256, V_SMEM>>>(ehs, bvalue);
        k_sample_attn<<<Nn / 2, 256, S3_SMEM>>>(rp, Walpha);
        k_gates256<<<dim3(8, 50), 256, GEMM_SMEM>>>();
        k_lstm_ew<<<Nn, 256>>>(c0, out, write3);
    }
}